// round 6
// baseline (speedup 1.0000x reference)
#include <cuda_runtime.h>
#include <math.h>
#include <stdint.h>

#define CDIM 512
#define BATCH 16
#define NPIX 1024
#define MCOLS (BATCH * NPIX)   // 16384

// ---------------------------------------------------------------------------
// Scratch (device globals)
// ---------------------------------------------------------------------------
__device__ float g_ht    [(size_t)CDIM * MCOLS];         // [c][m] groupnorm out (tf32)
__device__ float g_qkv   [(size_t)3 * CDIM * MCOLS];     // [o][m] (tf32)
__device__ float g_vT    [(size_t)MCOLS * CDIM];         // [tok][c] (tf32)
__device__ float g_attn  [(size_t)BATCH * NPIX * NPIX];  // [b][i][j]
__device__ float g_attnT [(size_t)BATCH * NPIX * NPIX];  // [b][j][i] (tf32)
__device__ float g_obuf  [(size_t)CDIM * MCOLS];         // [c][m] (tf32)
__device__ float g_wqkvT [(size_t)CDIM * 3 * CDIM];      // [c][o] (tf32)
__device__ float g_wprojT[(size_t)CDIM * CDIM];          // [c][o] (tf32)

// ---------------------------------------------------------------------------
// Helpers
// ---------------------------------------------------------------------------
__device__ __forceinline__ float ftf(float f) {  // fp32 -> tf32 (rna), kept in fp32
    uint32_t u; asm("cvt.rna.tf32.f32 %0, %1;" : "=r"(u) : "f"(f));
    return __uint_as_float(u);
}
__device__ __forceinline__ uint32_t sm_u32(const void* p) {
    uint32_t a;
    asm("{ .reg .u64 t; cvta.to.shared.u64 t, %1; cvt.u32.u64 %0, t; }" : "=r"(a) : "l"(p));
    return a;
}
__device__ __forceinline__ void cp16(uint32_t dst, const float* src) {
    asm volatile("cp.async.cg.shared.global [%0], [%1], 16;" :: "r"(dst), "l"(src));
}
__device__ __forceinline__ void mma_tf32(float c[4], const uint32_t a[4],
                                         const uint32_t b[2]) {
    asm volatile(
        "mma.sync.aligned.m16n8k8.row.col.f32.tf32.tf32.f32 "
        "{%0,%1,%2,%3}, {%4,%5,%6,%7}, {%8,%9}, {%0,%1,%2,%3};\n"
        : "+f"(c[0]), "+f"(c[1]), "+f"(c[2]), "+f"(c[3])
        : "r"(a[0]), "r"(a[1]), "r"(a[2]), "r"(a[3]), "r"(b[0]), "r"(b[1]));
}

// ---------------------------------------------------------------------------
// Small kernels
// ---------------------------------------------------------------------------
// batched transpose: in[bz][R][C] -> out[bz][C][R], rounds to tf32
__global__ void transpose_kernel(const float* __restrict__ in, float* __restrict__ out,
                                 int R, int C, long in_bs, long out_bs) {
    __shared__ float t[32][33];
    in  += (size_t)blockIdx.z * in_bs;
    out += (size_t)blockIdx.z * out_bs;
    const int tx = threadIdx.x & 31, ty = threadIdx.x >> 5;
    const int r0 = blockIdx.y * 32, c0 = blockIdx.x * 32;
    #pragma unroll
    for (int k = 0; k < 4; k++)
        t[ty + 8 * k][tx] = in[(size_t)(r0 + ty + 8 * k) * C + c0 + tx];
    __syncthreads();
    #pragma unroll
    for (int k = 0; k < 4; k++)
        out[(size_t)(c0 + ty + 8 * k) * R + r0 + tx] = ftf(t[tx][ty + 8 * k]);
}

__global__ void groupnorm_kernel(const float* __restrict__ x,
                                 const float* __restrict__ gamma,
                                 const float* __restrict__ beta,
                                 float* __restrict__ ht) {
    const int b = blockIdx.x >> 3;
    const int g = blockIdx.x & 7;
    const float* xb = x + ((size_t)b * CDIM + (size_t)g * 64) * NPIX;
    const int tid = threadIdx.x;
    const int NG = 64 * NPIX;

    float s = 0.f, ss = 0.f;
    for (int i = tid; i < NG; i += 256) {
        float v = xb[i];
        s += v; ss += v * v;
    }
    #pragma unroll
    for (int o = 16; o > 0; o >>= 1) {
        s  += __shfl_xor_sync(0xffffffffu, s, o);
        ss += __shfl_xor_sync(0xffffffffu, ss, o);
    }
    __shared__ float sh_s[8], sh_ss[8];
    if ((tid & 31) == 0) { sh_s[tid >> 5] = s; sh_ss[tid >> 5] = ss; }
    __syncthreads();
    if (tid < 32) {
        float s2  = (tid < 8) ? sh_s[tid]  : 0.f;
        float ss2 = (tid < 8) ? sh_ss[tid] : 0.f;
        #pragma unroll
        for (int o = 4; o > 0; o >>= 1) {
            s2  += __shfl_xor_sync(0xffffffffu, s2, o);
            ss2 += __shfl_xor_sync(0xffffffffu, ss2, o);
        }
        if (tid == 0) { sh_s[0] = s2; sh_ss[0] = ss2; }
    }
    __syncthreads();
    const float mean = sh_s[0] * (1.f / 65536.f);
    const float var  = sh_ss[0] * (1.f / 65536.f) - mean * mean;
    const float rstd = rsqrtf(var + 1e-5f);

    for (int i = tid; i < NG; i += 256) {
        int c = g * 64 + (i >> 10);
        int n = i & 1023;
        float v = (xb[i] - mean) * rstd;
        v = v * gamma[c] + beta[c];
        ht[(size_t)c * MCOLS + (size_t)b * NPIX + n] = ftf(v);
    }
}

__global__ void softmax_kernel(float* __restrict__ attn) {
    float* row = attn + (size_t)blockIdx.x * NPIX;
    const int tid = threadIdx.x;
    float v[4];
    float mx = -1e30f;
    #pragma unroll
    for (int i = 0; i < 4; i++) {
        v[i] = row[tid + i * 256];
        mx = fmaxf(mx, v[i]);
    }
    #pragma unroll
    for (int o = 16; o > 0; o >>= 1)
        mx = fmaxf(mx, __shfl_xor_sync(0xffffffffu, mx, o));
    __shared__ float sh[8];
    if ((tid & 31) == 0) sh[tid >> 5] = mx;
    __syncthreads();
    if (tid < 32) {
        float m2 = (tid < 8) ? sh[tid] : -1e30f;
        #pragma unroll
        for (int o = 4; o > 0; o >>= 1)
            m2 = fmaxf(m2, __shfl_xor_sync(0xffffffffu, m2, o));
        if (tid == 0) sh[0] = m2;
    }
    __syncthreads();
    mx = sh[0];

    float s = 0.f;
    #pragma unroll
    for (int i = 0; i < 4; i++) {
        v[i] = __expf(v[i] - mx);
        s += v[i];
    }
    #pragma unroll
    for (int o = 16; o > 0; o >>= 1)
        s += __shfl_xor_sync(0xffffffffu, s, o);
    __shared__ float sh2[8];
    if ((tid & 31) == 0) sh2[tid >> 5] = s;
    __syncthreads();
    if (tid < 32) {
        float s2 = (tid < 8) ? sh2[tid] : 0.f;
        #pragma unroll
        for (int o = 4; o > 0; o >>= 1)
            s2 += __shfl_xor_sync(0xffffffffu, s2, o);
        if (tid == 0) sh2[0] = s2;
    }
    __syncthreads();
    const float inv = 1.f / sh2[0];
    #pragma unroll
    for (int i = 0; i < 4; i++) row[tid + i * 256] = v[i] * inv;
}

// ---------------------------------------------------------------------------
// Pipelined TF32 mma.sync GEMM.
//   D[bz, m, n] = alpha * sum_k A[bz, k, m] * B[bz, k, n] (+bias[m]) (+resid)
// A: k-major rows of contiguous m, row stride a_rs; B likewise for n.
// Tile 128x256x16, 512 threads, 16 warps (2m x 8n), warp tile 64x32.
// 4-stage cp.async, register-double-buffered fragments.
// Requires M%128==0, N%256==0, K%16==0.
// ---------------------------------------------------------------------------
#define BM 128
#define BN 256
#define BK 16
#define STAGES 4
#define LDA 136   // BM + 8 pad (floats)
#define LDB 264   // BN + 8 pad
#define A_STG (BK * LDA)
#define B_STG (BK * LDB)
#define SMEM_BYTES (STAGES * (A_STG + B_STG) * 4)

__global__ __launch_bounds__(512, 1)
void tc_gemm(const float* __restrict__ A, const float* __restrict__ B,
             float* __restrict__ C,
             const float* __restrict__ bias_m, const float* __restrict__ resid,
             int Kdim, long a_rs, long a_zs, long b_rs, long b_zs,
             long c_ms, long c_zs, float alpha, int round_out) {
    extern __shared__ uint32_t smem[];
    uint32_t* Asm = smem;                     // [STAGES][BK][LDA]
    uint32_t* Bsm = smem + STAGES * A_STG;    // [STAGES][BK][LDB]

    const int tid = threadIdx.x, warp = tid >> 5, lane = tid & 31;
    const int gid = lane >> 2, tig = lane & 3;
    const int bx = blockIdx.x, by = blockIdx.y, bz = blockIdx.z;
    const int wm = (warp & 1) * 64;
    const int wn = (warp >> 1) * 32;

    const float* Ab = A + (size_t)bz * a_zs + (size_t)by * BM;
    const float* Bb = B + (size_t)bz * b_zs + (size_t)bx * BN;

    float acc[4][4][4];
    #pragma unroll
    for (int i = 0; i < 4; i++)
        #pragma unroll
        for (int j = 0; j < 4; j++)
            #pragma unroll
            for (int r = 0; r < 4; r++) acc[i][j][r] = 0.f;

    // fill stage (t % STAGES) with k-slice t
    auto fill = [&](int t) {
        const int s = t % STAGES;
        {   // A: 512 chunks of 16B, 1 per thread
            const float* ag = Ab + (size_t)t * BK * a_rs;
            const uint32_t ad = sm_u32(Asm + s * A_STG);
            int k = tid >> 5, m4 = (lane) * 4;
            cp16(ad + (uint32_t)(k * LDA + m4) * 4, ag + (size_t)k * a_rs + m4);
        }
        {   // B: 1024 chunks, 2 per thread
            const float* bg = Bb + (size_t)t * BK * b_rs;
            const uint32_t bd = sm_u32(Bsm + s * B_STG);
            #pragma unroll
            for (int i = 0; i < 2; i++) {
                int idx = tid + i * 512;
                int k = idx >> 6, n4 = (idx & 63) * 4;
                cp16(bd + (uint32_t)(k * LDB + n4) * 4, bg + (size_t)k * b_rs + n4);
            }
        }
        asm volatile("cp.async.commit_group;" ::: "memory");
    };

    const int T = Kdim / BK;
    fill(0);
    if (T > 1) fill(1);
    if (T > 2) fill(2);

    uint32_t af[2][4][4], bf[2][4][2];

    auto load_frags = [&](const uint32_t* As, const uint32_t* Bs, int ks, int buf) {
        const uint32_t* ar0 = As + (ks + tig) * LDA;
        const uint32_t* ar1 = As + (ks + tig + 4) * LDA;
        const uint32_t* br0 = Bs + (ks + tig) * LDB;
        const uint32_t* br1 = Bs + (ks + tig + 4) * LDB;
        #pragma unroll
        for (int i = 0; i < 4; i++) {
            const int m = wm + i * 16 + gid;
            af[buf][i][0] = ar0[m];
            af[buf][i][1] = ar0[m + 8];
            af[buf][i][2] = ar1[m];
            af[buf][i][3] = ar1[m + 8];
        }
        #pragma unroll
        for (int j = 0; j < 4; j++) {
            const int n = wn + j * 8 + gid;
            bf[buf][j][0] = br0[n];
            bf[buf][j][1] = br1[n];
        }
    };

    for (int t = 0; t < T; t++) {
        if (t + 3 <= T)      asm volatile("cp.async.wait_group 2;" ::: "memory");
        else if (t + 2 == T) asm volatile("cp.async.wait_group 1;" ::: "memory");
        else                 asm volatile("cp.async.wait_group 0;" ::: "memory");
        __syncthreads();

        if (t + 3 < T) fill(t + 3);

        const int s = t % STAGES;
        const uint32_t* As = Asm + s * A_STG;
        const uint32_t* Bs = Bsm + s * B_STG;

        load_frags(As, Bs, 0, 0);
        load_frags(As, Bs, 8, 1);   // prefetch second slice while first computes
        #pragma unroll
        for (int i = 0; i < 4; i++)
            #pragma unroll
            for (int j = 0; j < 4; j++)
                mma_tf32(acc[i][j], af[0][i], bf[0][j]);
        #pragma unroll
        for (int i = 0; i < 4; i++)
            #pragma unroll
            for (int j = 0; j < 4; j++)
                mma_tf32(acc[i][j], af[1][i], bf[1][j]);

        __syncthreads();
    }

    // ---- epilogue ----
    #pragma unroll
    for (int i = 0; i < 4; i++) {
        const int m0 = by * BM + wm + i * 16 + gid;
        const float bv0 = bias_m ? bias_m[m0] : 0.f;
        const float bv1 = bias_m ? bias_m[m0 + 8] : 0.f;
        #pragma unroll
        for (int j = 0; j < 4; j++) {
            const int n0 = bx * BN + wn + j * 8 + tig * 2;
            size_t o0 = (size_t)bz * c_zs + (size_t)m0 * c_ms + n0;
            size_t o1 = o0 + 8 * c_ms;
            float2 v0, v1;
            v0.x = acc[i][j][0] * alpha + bv0;
            v0.y = acc[i][j][1] * alpha + bv0;
            v1.x = acc[i][j][2] * alpha + bv1;
            v1.y = acc[i][j][3] * alpha + bv1;
            if (resid) {
                v0.x += resid[o0];     v0.y += resid[o0 + 1];
                v1.x += resid[o1];     v1.y += resid[o1 + 1];
            }
            if (round_out) {
                v0.x = ftf(v0.x); v0.y = ftf(v0.y);
                v1.x = ftf(v1.x); v1.y = ftf(v1.y);
            }
            *(float2*)(C + o0) = v0;
            *(float2*)(C + o1) = v1;
        }
    }
}

// ---------------------------------------------------------------------------
// Launch
// ---------------------------------------------------------------------------
extern "C" void kernel_launch(void* const* d_in, const int* in_sizes, int n_in,
                              void* d_out, int out_size) {
    const float* x      = (const float*)d_in[0];
    const float* gamma  = (const float*)d_in[1];
    const float* beta   = (const float*)d_in[2];
    const float* w_qkv  = (const float*)d_in[3];
    const float* b_qkv  = (const float*)d_in[4];
    const float* w_proj = (const float*)d_in[5];
    const float* b_proj = (const float*)d_in[6];
    float* out = (float*)d_out;

    float *ht, *qkv, *vT, *attn, *attnT, *obuf, *wqkvT, *wprojT;
    cudaGetSymbolAddress((void**)&ht,     g_ht);
    cudaGetSymbolAddress((void**)&qkv,    g_qkv);
    cudaGetSymbolAddress((void**)&vT,     g_vT);
    cudaGetSymbolAddress((void**)&attn,   g_attn);
    cudaGetSymbolAddress((void**)&attnT,  g_attnT);
    cudaGetSymbolAddress((void**)&obuf,   g_obuf);
    cudaGetSymbolAddress((void**)&wqkvT,  g_wqkvT);
    cudaGetSymbolAddress((void**)&wprojT, g_wprojT);

    cudaFuncSetAttribute(tc_gemm, cudaFuncAttributeMaxDynamicSharedMemorySize, SMEM_BYTES);

    const float scale = 1.0f / sqrtf((float)CDIM);

    // 0) transpose + round weights
    transpose_kernel<<<dim3(512 / 32, 1536 / 32, 1), 256>>>(w_qkv, wqkvT, 1536, 512, 0, 0);
    transpose_kernel<<<dim3(512 / 32, 512 / 32, 1), 256>>>(w_proj, wprojT, 512, 512, 0, 0);

    // 1) GroupNorm -> ht[c][m] (tf32-rounded)
    groupnorm_kernel<<<BATCH * 8, 256>>>(x, gamma, beta, ht);

    // 2) QKV: qkv[o][m] = sum_c wqkvT[c][o] * ht[c][m] + b_qkv[o]
    tc_gemm<<<dim3(MCOLS / BN, 1536 / BM, 1), 512, SMEM_BYTES>>>(
        wqkvT, ht, qkv, b_qkv, nullptr,
        CDIM, /*a_rs*/ 1536, 0, /*b_rs*/ MCOLS, 0,
        /*c_ms*/ MCOLS, 0, 1.0f, /*round*/ 1);

    // 3) Scores: attn[b][i][j] = scale * sum_c q[c][b*1024+i] * k[c][b*1024+j]
    tc_gemm<<<dim3(NPIX / BN, NPIX / BM, BATCH), 512, SMEM_BYTES>>>(
        qkv, qkv + (size_t)CDIM * MCOLS, attn, nullptr, nullptr,
        CDIM, /*a_rs*/ MCOLS, /*a_zs*/ NPIX, /*b_rs*/ MCOLS, /*b_zs*/ NPIX,
        /*c_ms*/ NPIX, (long)NPIX * NPIX, scale, 0);

    // 4) Softmax rows
    softmax_kernel<<<BATCH * NPIX, 256>>>(attn);

    // 5) transposes: attn -> attnT[b][j][i]; v -> vT[tok][c]
    transpose_kernel<<<dim3(NPIX / 32, NPIX / 32, BATCH), 256>>>(
        attn, attnT, NPIX, NPIX, (long)NPIX * NPIX, (long)NPIX * NPIX);
    transpose_kernel<<<dim3(MCOLS / 32, CDIM / 32, 1), 256>>>(
        qkv + (size_t)2 * CDIM * MCOLS, vT, CDIM, MCOLS, 0, 0);

    // 6) PV: obuf[c][b*1024+i] = sum_j vT[b*1024+j][c] * attnT[b][j][i]
    tc_gemm<<<dim3(NPIX / BN, CDIM / BM, BATCH), 512, SMEM_BYTES>>>(
        vT, attnT, obuf, nullptr, nullptr,
        NPIX, /*a_rs*/ CDIM, /*a_zs*/ (long)NPIX * CDIM,
        /*b_rs*/ NPIX, /*b_zs*/ (long)NPIX * NPIX,
        /*c_ms*/ MCOLS, /*c_zs*/ NPIX, 1.0f, /*round*/ 1);

    // 7) Proj: out[b][o][n] = sum_c wprojT[c][o] * obuf[c][b*1024+n] + b_proj[o] + x
    tc_gemm<<<dim3(NPIX / BN, CDIM / BM, BATCH), 512, SMEM_BYTES>>>(
        wprojT, obuf, out, b_proj, x,
        CDIM, /*a_rs*/ CDIM, 0, /*b_rs*/ MCOLS, /*b_zs*/ NPIX,
        /*c_ms*/ NPIX, (long)CDIM * NPIX, 1.0f, 0);
}

// round 7
// speedup vs baseline: 2.8863x; 2.8863x over previous
#include <cuda_runtime.h>
#include <cuda_fp16.h>
#include <math.h>
#include <stdint.h>

#define CDIM 512
#define BATCH 16
#define NPIX 1024
#define MCOLS (BATCH * NPIX)   // 16384

// ---------------------------------------------------------------------------
// Scratch (device globals)
// ---------------------------------------------------------------------------
__device__ float  g_ht    [(size_t)CDIM * MCOLS];          // [c][t] fp32 groupnorm out
__device__ __half g_hT    [(size_t)MCOLS * CDIM];          // [t][c]
__device__ __half g_wqkvH [(size_t)3 * CDIM * CDIM];       // [o][c]
__device__ __half g_wprojH[(size_t)CDIM * CDIM];           // [o][c]
__device__ __half g_qkvT  [(size_t)MCOLS * 3 * CDIM];      // [t][o]  q|k|v
__device__ float  g_attn  [(size_t)BATCH * NPIX * NPIX];   // [b][i][j] fp32 scores
__device__ __half g_attnH [(size_t)BATCH * NPIX * NPIX];   // [b][i][j] softmaxed
__device__ __half g_vC    [(size_t)CDIM * MCOLS];          // [c][t]
__device__ __half g_obT   [(size_t)MCOLS * CDIM];          // [t][c]

// ---------------------------------------------------------------------------
// Helpers
// ---------------------------------------------------------------------------
__device__ __forceinline__ uint32_t sm_u32(const void* p) {
    uint32_t a;
    asm("{ .reg .u64 t; cvta.to.shared.u64 t, %1; cvt.u32.u64 %0, t; }" : "=r"(a) : "l"(p));
    return a;
}
__device__ __forceinline__ void cp16(uint32_t dst, const void* src) {
    asm volatile("cp.async.cg.shared.global [%0], [%1], 16;" :: "r"(dst), "l"(src));
}
__device__ __forceinline__ void mma_f16(float c[4], const uint32_t a[4],
                                        const uint32_t b[2]) {
    asm volatile(
        "mma.sync.aligned.m16n8k16.row.col.f32.f16.f16.f32 "
        "{%0,%1,%2,%3}, {%4,%5,%6,%7}, {%8,%9}, {%0,%1,%2,%3};\n"
        : "+f"(c[0]), "+f"(c[1]), "+f"(c[2]), "+f"(c[3])
        : "r"(a[0]), "r"(a[1]), "r"(a[2]), "r"(a[3]), "r"(b[0]), "r"(b[1]));
}

// ---------------------------------------------------------------------------
// Small kernels
// ---------------------------------------------------------------------------
__global__ void convert_h_kernel(const float* __restrict__ in, __half* __restrict__ out, int n) {
    int i = blockIdx.x * 256 + threadIdx.x;
    if (i < n) out[i] = __float2half(in[i]);
}

// in[R][C] fp32 -> out[C][R] half
__global__ void transpose_f2h(const float* __restrict__ in, __half* __restrict__ out,
                              int R, int C) {
    __shared__ float t[32][33];
    const int tx = threadIdx.x & 31, ty = threadIdx.x >> 5;
    const int r0 = blockIdx.y * 32, c0 = blockIdx.x * 32;
    #pragma unroll
    for (int k = 0; k < 4; k++)
        t[ty + 8 * k][tx] = in[(size_t)(r0 + ty + 8 * k) * C + c0 + tx];
    __syncthreads();
    #pragma unroll
    for (int k = 0; k < 4; k++)
        out[(size_t)(c0 + ty + 8 * k) * R + r0 + tx] = __float2half(t[tx][ty + 8 * k]);
}

// in rows R x cols C (row stride in_rs, half) -> out[C][R] (row stride out_rs)
__global__ void transpose_h2h(const __half* __restrict__ in, __half* __restrict__ out,
                              int R, long in_rs, long out_rs) {
    __shared__ __half t[32][34];
    const int tx = threadIdx.x & 31, ty = threadIdx.x >> 5;
    const int r0 = blockIdx.y * 32, c0 = blockIdx.x * 32;
    #pragma unroll
    for (int k = 0; k < 4; k++)
        t[ty + 8 * k][tx] = in[(size_t)(r0 + ty + 8 * k) * in_rs + c0 + tx];
    __syncthreads();
    #pragma unroll
    for (int k = 0; k < 4; k++)
        out[(size_t)(c0 + ty + 8 * k) * out_rs + r0 + tx] = t[tx][ty + 8 * k];
}

__global__ void groupnorm_kernel(const float* __restrict__ x,
                                 const float* __restrict__ gamma,
                                 const float* __restrict__ beta,
                                 float* __restrict__ ht) {
    const int b = blockIdx.x >> 3;
    const int g = blockIdx.x & 7;
    const float* xb = x + ((size_t)b * CDIM + (size_t)g * 64) * NPIX;
    const int tid = threadIdx.x;
    const int NG = 64 * NPIX;

    float s = 0.f, ss = 0.f;
    for (int i = tid; i < NG; i += 256) {
        float v = xb[i];
        s += v; ss += v * v;
    }
    #pragma unroll
    for (int o = 16; o > 0; o >>= 1) {
        s  += __shfl_xor_sync(0xffffffffu, s, o);
        ss += __shfl_xor_sync(0xffffffffu, ss, o);
    }
    __shared__ float sh_s[8], sh_ss[8];
    if ((tid & 31) == 0) { sh_s[tid >> 5] = s; sh_ss[tid >> 5] = ss; }
    __syncthreads();
    if (tid < 32) {
        float s2  = (tid < 8) ? sh_s[tid]  : 0.f;
        float ss2 = (tid < 8) ? sh_ss[tid] : 0.f;
        #pragma unroll
        for (int o = 4; o > 0; o >>= 1) {
            s2  += __shfl_xor_sync(0xffffffffu, s2, o);
            ss2 += __shfl_xor_sync(0xffffffffu, ss2, o);
        }
        if (tid == 0) { sh_s[0] = s2; sh_ss[0] = ss2; }
    }
    __syncthreads();
    const float mean = sh_s[0] * (1.f / 65536.f);
    const float var  = sh_ss[0] * (1.f / 65536.f) - mean * mean;
    const float rstd = rsqrtf(var + 1e-5f);

    for (int i = tid; i < NG; i += 256) {
        int c = g * 64 + (i >> 10);
        int n = i & 1023;
        float v = (xb[i] - mean) * rstd;
        v = v * gamma[c] + beta[c];
        ht[(size_t)c * MCOLS + (size_t)b * NPIX + n] = v;
    }
}

// fp32 scores in -> half probabilities out
__global__ void softmax_kernel(const float* __restrict__ attn, __half* __restrict__ attnH) {
    const float* row = attn + (size_t)blockIdx.x * NPIX;
    __half* rowo = attnH + (size_t)blockIdx.x * NPIX;
    const int tid = threadIdx.x;
    float v[4];
    float mx = -1e30f;
    #pragma unroll
    for (int i = 0; i < 4; i++) {
        v[i] = row[tid + i * 256];
        mx = fmaxf(mx, v[i]);
    }
    #pragma unroll
    for (int o = 16; o > 0; o >>= 1)
        mx = fmaxf(mx, __shfl_xor_sync(0xffffffffu, mx, o));
    __shared__ float sh[8];
    if ((tid & 31) == 0) sh[tid >> 5] = mx;
    __syncthreads();
    if (tid < 32) {
        float m2 = (tid < 8) ? sh[tid] : -1e30f;
        #pragma unroll
        for (int o = 4; o > 0; o >>= 1)
            m2 = fmaxf(m2, __shfl_xor_sync(0xffffffffu, m2, o));
        if (tid == 0) sh[0] = m2;
    }
    __syncthreads();
    mx = sh[0];

    float s = 0.f;
    #pragma unroll
    for (int i = 0; i < 4; i++) {
        v[i] = __expf(v[i] - mx);
        s += v[i];
    }
    #pragma unroll
    for (int o = 16; o > 0; o >>= 1)
        s += __shfl_xor_sync(0xffffffffu, s, o);
    __shared__ float sh2[8];
    if ((tid & 31) == 0) sh2[tid >> 5] = s;
    __syncthreads();
    if (tid < 32) {
        float s2 = (tid < 8) ? sh2[tid] : 0.f;
        #pragma unroll
        for (int o = 4; o > 0; o >>= 1)
            s2 += __shfl_xor_sync(0xffffffffu, s2, o);
        if (tid == 0) sh2[0] = s2;
    }
    __syncthreads();
    const float inv = 1.f / sh2[0];
    #pragma unroll
    for (int i = 0; i < 4; i++) rowo[tid + i * 256] = __float2half(v[i] * inv);
}

// ---------------------------------------------------------------------------
// FP16 NT GEMM (fp32 accumulate):
//   D[bz, m, n] = alpha * sum_k A[m][k] * B[n][k] (+bias_m[m]) (+bias_n[n]) (+resid)
// A: [M rows][K] k-contiguous half, row stride a_rs (halves).
// B: [N rows][K] k-contiguous half, row stride b_rs.
// Tile 128x256x64, 256 threads, 8 warps (2m x 4n), warp tile 64x64.
// 3-stage cp.async. M%128==0, N%256==0, K%64==0. Output fp32 (Cf) or half (Ch).
// ---------------------------------------------------------------------------
#define BM 128
#define BN 256
#define BKH 64
#define STAGES 3
#define LDAH 72                    // halves per A smem row (64 + 8 pad)
#define A_STG_B (BM * LDAH * 2)    // 18432 bytes
#define B_STG_B (BN * LDAH * 2)    // 36864 bytes
#define SMEM_BYTES (STAGES * (A_STG_B + B_STG_B))

__global__ __launch_bounds__(256, 1)
void hgemm(const __half* __restrict__ A, const __half* __restrict__ B,
           float* __restrict__ Cf, __half* __restrict__ Ch,
           const float* __restrict__ bias_m, const float* __restrict__ bias_n,
           const float* __restrict__ resid,
           int Kdim, long a_rs, long a_zs, long b_rs, long b_zs,
           long c_ms, long c_zs, float alpha) {
    extern __shared__ char smem_raw[];
    const uint32_t as_base = sm_u32(smem_raw);
    const uint32_t bs_base = as_base + STAGES * A_STG_B;
    const uint32_t* smw = (const uint32_t*)smem_raw;

    const int tid = threadIdx.x, warp = tid >> 5, lane = tid & 31;
    const int gid = lane >> 2, tig = lane & 3;
    const int bx = blockIdx.x, by = blockIdx.y, bz = blockIdx.z;
    const int wm = (warp & 1) * 64;
    const int wn = (warp >> 1) * 64;

    const __half* Ab = A + (size_t)bz * a_zs + (size_t)by * BM * a_rs;
    const __half* Bb = B + (size_t)bz * b_zs + (size_t)bx * BN * b_rs;

    float acc[4][8][4];
    #pragma unroll
    for (int i = 0; i < 4; i++)
        #pragma unroll
        for (int j = 0; j < 8; j++)
            #pragma unroll
            for (int r = 0; r < 4; r++) acc[i][j][r] = 0.f;

    // fill stage (t % STAGES) with k-slice t (64 halves of k per row)
    auto fill = [&](int t) {
        const int s = t % STAGES;
        const __half* ag = Ab + (size_t)t * BKH;
        const uint32_t ad = as_base + s * A_STG_B;
        #pragma unroll
        for (int i = 0; i < 4; i++) {
            int idx = tid + i * 256;            // 1024 chunks: r=idx>>3, g=idx&7
            int r = idx >> 3, g = idx & 7;
            cp16(ad + (uint32_t)(r * (LDAH * 2) + g * 16), ag + (size_t)r * a_rs + g * 8);
        }
        const __half* bg = Bb + (size_t)t * BKH;
        const uint32_t bd = bs_base + s * B_STG_B;
        #pragma unroll
        for (int i = 0; i < 8; i++) {
            int idx = tid + i * 256;            // 2048 chunks
            int r = idx >> 3, g = idx & 7;
            cp16(bd + (uint32_t)(r * (LDAH * 2) + g * 16), bg + (size_t)r * b_rs + g * 8);
        }
        asm volatile("cp.async.commit_group;" ::: "memory");
    };

    const int T = Kdim / BKH;
    fill(0);
    if (T > 1) fill(1);

    const int LW = LDAH / 2;   // 36 words per smem row
    const uint32_t* AsW0 = smw;                               // A stages base (words)
    const uint32_t* BsW0 = smw + STAGES * (A_STG_B / 4);

    for (int t = 0; t < T; t++) {
        if (t < T - 1) asm volatile("cp.async.wait_group 1;" ::: "memory");
        else           asm volatile("cp.async.wait_group 0;" ::: "memory");
        __syncthreads();

        if (t + 2 < T) fill(t + 2);

        const int s = t % STAGES;
        const uint32_t* As = AsW0 + s * (A_STG_B / 4);
        const uint32_t* Bs = BsW0 + s * (B_STG_B / 4);

        #pragma unroll
        for (int sl = 0; sl < 4; sl++) {        // 4 x k16 slices
            const int kw = sl * 8;              // word offset within row
            uint32_t af[4][4], bf[8][2];
            #pragma unroll
            for (int i = 0; i < 4; i++) {
                const int m = wm + i * 16 + gid;
                const uint32_t* r0 = As + m * LW + kw + tig;
                const uint32_t* r1 = As + (m + 8) * LW + kw + tig;
                af[i][0] = r0[0];
                af[i][1] = r1[0];
                af[i][2] = r0[4];
                af[i][3] = r1[4];
            }
            #pragma unroll
            for (int j = 0; j < 8; j++) {
                const int n = wn + j * 8 + gid;
                const uint32_t* r0 = Bs + n * LW + kw + tig;
                bf[j][0] = r0[0];
                bf[j][1] = r0[4];
            }
            #pragma unroll
            for (int i = 0; i < 4; i++)
                #pragma unroll
                for (int j = 0; j < 8; j++)
                    mma_f16(acc[i][j], af[i], bf[j]);
        }
    }

    // ---- epilogue ----
    #pragma unroll
    for (int i = 0; i < 4; i++) {
        const int m0 = by * BM + wm + i * 16 + gid;
        const float bv0 = bias_m ? bias_m[m0] : 0.f;
        const float bv1 = bias_m ? bias_m[m0 + 8] : 0.f;
        #pragma unroll
        for (int j = 0; j < 8; j++) {
            const int n0 = bx * BN + wn + j * 8 + tig * 2;
            const float bn0 = bias_n ? bias_n[n0] : 0.f;
            const float bn1 = bias_n ? bias_n[n0 + 1] : 0.f;
            size_t o0 = (size_t)bz * c_zs + (size_t)m0 * c_ms + n0;
            size_t o1 = o0 + 8 * c_ms;
            float v0 = acc[i][j][0] * alpha + bv0 + bn0;
            float v1 = acc[i][j][1] * alpha + bv0 + bn1;
            float v2 = acc[i][j][2] * alpha + bv1 + bn0;
            float v3 = acc[i][j][3] * alpha + bv1 + bn1;
            if (resid) {
                v0 += resid[o0]; v1 += resid[o0 + 1];
                v2 += resid[o1]; v3 += resid[o1 + 1];
            }
            if (Ch) {
                *(__half2*)(Ch + o0) = __floats2half2_rn(v0, v1);
                *(__half2*)(Ch + o1) = __floats2half2_rn(v2, v3);
            } else {
                *(float2*)(Cf + o0) = make_float2(v0, v1);
                *(float2*)(Cf + o1) = make_float2(v2, v3);
            }
        }
    }
}

// ---------------------------------------------------------------------------
// Launch
// ---------------------------------------------------------------------------
extern "C" void kernel_launch(void* const* d_in, const int* in_sizes, int n_in,
                              void* d_out, int out_size) {
    const float* x      = (const float*)d_in[0];
    const float* gamma  = (const float*)d_in[1];
    const float* beta   = (const float*)d_in[2];
    const float* w_qkv  = (const float*)d_in[3];
    const float* b_qkv  = (const float*)d_in[4];
    const float* w_proj = (const float*)d_in[5];
    const float* b_proj = (const float*)d_in[6];
    float* out = (float*)d_out;

    float *ht, *attn;
    __half *hT, *wqkvH, *wprojH, *qkvT, *attnH, *vC, *obT;
    cudaGetSymbolAddress((void**)&ht,     g_ht);
    cudaGetSymbolAddress((void**)&hT,     g_hT);
    cudaGetSymbolAddress((void**)&wqkvH,  g_wqkvH);
    cudaGetSymbolAddress((void**)&wprojH, g_wprojH);
    cudaGetSymbolAddress((void**)&qkvT,   g_qkvT);
    cudaGetSymbolAddress((void**)&attn,   g_attn);
    cudaGetSymbolAddress((void**)&attnH,  g_attnH);
    cudaGetSymbolAddress((void**)&vC,     g_vC);
    cudaGetSymbolAddress((void**)&obT,    g_obT);

    cudaFuncSetAttribute(hgemm, cudaFuncAttributeMaxDynamicSharedMemorySize, SMEM_BYTES);

    const float scale = 1.0f / sqrtf((float)CDIM);

    // 0) convert weights to half (no transpose needed: [o][c] is NT B operand)
    convert_h_kernel<<<(3 * CDIM * CDIM) / 256, 256>>>(w_qkv, wqkvH, 3 * CDIM * CDIM);
    convert_h_kernel<<<(CDIM * CDIM) / 256, 256>>>(w_proj, wprojH, CDIM * CDIM);

    // 1) GroupNorm -> ht[c][t] fp32
    groupnorm_kernel<<<BATCH * 8, 256>>>(x, gamma, beta, ht);

    // 2) ht[c][t] -> hT[t][c] half
    transpose_f2h<<<dim3(MCOLS / 32, CDIM / 32), 256>>>(ht, hT, CDIM, MCOLS);

    // 3) QKV: qkvT[t][o] = sum_c hT[t][c] * wqkvH[o][c] + b_qkv[o]   (M=16384,N=1536,K=512)
    hgemm<<<dim3(1536 / BN, MCOLS / BM, 1), 256, SMEM_BYTES>>>(
        hT, wqkvH, nullptr, qkvT, nullptr, b_qkv, nullptr,
        CDIM, /*a_rs*/ CDIM, 0, /*b_rs*/ CDIM, 0,
        /*c_ms*/ 1536, 0, 1.0f);

    // 4) Scores: attn[b][i][j] = scale * sum_c q[i][c] * k[j][c]   (batched, M=N=1024,K=512)
    hgemm<<<dim3(NPIX / BN, NPIX / BM, BATCH), 256, SMEM_BYTES>>>(
        qkvT, qkvT + 512, attn, nullptr, nullptr, nullptr, nullptr,
        CDIM, /*a_rs*/ 1536, /*a_zs*/ (long)NPIX * 1536,
        /*b_rs*/ 1536, /*b_zs*/ (long)NPIX * 1536,
        /*c_ms*/ NPIX, (long)NPIX * NPIX, scale);

    // 5) Softmax fp32 -> half probs
    softmax_kernel<<<BATCH * NPIX, 256>>>(attn, attnH);

    // 6) v part of qkvT [t][1024+c] -> vC[c][t]
    transpose_h2h<<<dim3(CDIM / 32, MCOLS / 32), 256>>>(
        qkvT + 1024, vC, MCOLS, /*in_rs*/ 1536, /*out_rs*/ MCOLS);

    // 7) PV: obT[b*1024+i][c] = sum_j attnH[b][i][j] * vC[c][b*1024+j]  (M=1024,N=512,K=1024)
    hgemm<<<dim3(CDIM / BN, NPIX / BM, BATCH), 256, SMEM_BYTES>>>(
        attnH, vC, nullptr, obT, nullptr, nullptr, nullptr,
        NPIX, /*a_rs*/ NPIX, /*a_zs*/ (long)NPIX * NPIX,
        /*b_rs*/ MCOLS, /*b_zs*/ (long)NPIX,
        /*c_ms*/ CDIM, (long)NPIX * CDIM, 1.0f);

    // 8) Proj: out[b][o][n] = sum_c wprojH[o][c] * obT[b*1024+n][c] + b_proj[o] + x
    hgemm<<<dim3(NPIX / BN, CDIM / BM, BATCH), 256, SMEM_BYTES>>>(
        wprojH, obT, out, nullptr, b_proj, nullptr, x,
        CDIM, /*a_rs*/ CDIM, 0, /*b_rs*/ CDIM, /*b_zs*/ (long)NPIX * CDIM,
        /*c_ms*/ NPIX, (long)CDIM * NPIX, 1.0f);
}

// round 8
// speedup vs baseline: 2.9614x; 1.0260x over previous
#include <cuda_runtime.h>
#include <cuda_fp16.h>
#include <math.h>
#include <stdint.h>

#define CDIM 512
#define BATCH 16
#define NPIX 1024
#define MCOLS (BATCH * NPIX)   // 16384

// ---------------------------------------------------------------------------
// Scratch (device globals)
// ---------------------------------------------------------------------------
__device__ float  g_ht    [(size_t)CDIM * MCOLS];          // [c][t] fp32 groupnorm out
__device__ __half g_hT    [(size_t)MCOLS * CDIM];          // [t][c]
__device__ __half g_wqkvH [(size_t)3 * CDIM * CDIM];       // [o][c]
__device__ __half g_wprojH[(size_t)CDIM * CDIM];           // [o][c]
__device__ __half g_qkvT  [(size_t)MCOLS * 3 * CDIM];      // [t][o]  q|k|v
__device__ float  g_attn  [(size_t)BATCH * NPIX * NPIX];   // [b][i][j] fp32 scores
__device__ __half g_attnH [(size_t)BATCH * NPIX * NPIX];   // [b][i][j] softmaxed
__device__ __half g_vC    [(size_t)CDIM * MCOLS];          // [c][t]
__device__ __half g_obT   [(size_t)MCOLS * CDIM];          // [t][c]

// ---------------------------------------------------------------------------
// Helpers
// ---------------------------------------------------------------------------
__device__ __forceinline__ uint32_t sm_u32(const void* p) {
    uint32_t a;
    asm("{ .reg .u64 t; cvta.to.shared.u64 t, %1; cvt.u32.u64 %0, t; }" : "=r"(a) : "l"(p));
    return a;
}
__device__ __forceinline__ void cp16(uint32_t dst, const void* src) {
    asm volatile("cp.async.cg.shared.global [%0], [%1], 16;" :: "r"(dst), "l"(src));
}
__device__ __forceinline__ void mma_f16(float c[4], const uint32_t a[4],
                                        const uint32_t b[2]) {
    asm volatile(
        "mma.sync.aligned.m16n8k16.row.col.f32.f16.f16.f32 "
        "{%0,%1,%2,%3}, {%4,%5,%6,%7}, {%8,%9}, {%0,%1,%2,%3};\n"
        : "+f"(c[0]), "+f"(c[1]), "+f"(c[2]), "+f"(c[3])
        : "r"(a[0]), "r"(a[1]), "r"(a[2]), "r"(a[3]), "r"(b[0]), "r"(b[1]));
}
__device__ __forceinline__ void ldmx4(uint32_t r[4], uint32_t addr) {
    asm volatile("ldmatrix.sync.aligned.m8n8.x4.shared.b16 {%0,%1,%2,%3}, [%4];"
                 : "=r"(r[0]), "=r"(r[1]), "=r"(r[2]), "=r"(r[3]) : "r"(addr));
}

// ---------------------------------------------------------------------------
// Small kernels
// ---------------------------------------------------------------------------
__global__ void convert_h_kernel(const float* __restrict__ in, __half* __restrict__ out, int n) {
    int i = blockIdx.x * 256 + threadIdx.x;
    if (i < n) out[i] = __float2half(in[i]);
}

// in[R][C] fp32 -> out[C][R] half
__global__ void transpose_f2h(const float* __restrict__ in, __half* __restrict__ out,
                              int R, int C) {
    __shared__ float t[32][33];
    const int tx = threadIdx.x & 31, ty = threadIdx.x >> 5;
    const int r0 = blockIdx.y * 32, c0 = blockIdx.x * 32;
    #pragma unroll
    for (int k = 0; k < 4; k++)
        t[ty + 8 * k][tx] = in[(size_t)(r0 + ty + 8 * k) * C + c0 + tx];
    __syncthreads();
    #pragma unroll
    for (int k = 0; k < 4; k++)
        out[(size_t)(c0 + ty + 8 * k) * R + r0 + tx] = __float2half(t[tx][ty + 8 * k]);
}

// in rows R x cols C (row stride in_rs, half) -> out[C][R] (row stride out_rs)
__global__ void transpose_h2h(const __half* __restrict__ in, __half* __restrict__ out,
                              int R, long in_rs, long out_rs) {
    __shared__ __half t[32][34];
    const int tx = threadIdx.x & 31, ty = threadIdx.x >> 5;
    const int r0 = blockIdx.y * 32, c0 = blockIdx.x * 32;
    #pragma unroll
    for (int k = 0; k < 4; k++)
        t[ty + 8 * k][tx] = in[(size_t)(r0 + ty + 8 * k) * in_rs + c0 + tx];
    __syncthreads();
    #pragma unroll
    for (int k = 0; k < 4; k++)
        out[(size_t)(c0 + ty + 8 * k) * out_rs + r0 + tx] = t[tx][ty + 8 * k];
}

__global__ void groupnorm_kernel(const float* __restrict__ x,
                                 const float* __restrict__ gamma,
                                 const float* __restrict__ beta,
                                 float* __restrict__ ht) {
    const int b = blockIdx.x >> 3;
    const int g = blockIdx.x & 7;
    const float* xb = x + ((size_t)b * CDIM + (size_t)g * 64) * NPIX;
    const int tid = threadIdx.x;
    const int NG = 64 * NPIX;

    float s = 0.f, ss = 0.f;
    for (int i = tid; i < NG; i += 256) {
        float v = xb[i];
        s += v; ss += v * v;
    }
    #pragma unroll
    for (int o = 16; o > 0; o >>= 1) {
        s  += __shfl_xor_sync(0xffffffffu, s, o);
        ss += __shfl_xor_sync(0xffffffffu, ss, o);
    }
    __shared__ float sh_s[8], sh_ss[8];
    if ((tid & 31) == 0) { sh_s[tid >> 5] = s; sh_ss[tid >> 5] = ss; }
    __syncthreads();
    if (tid < 32) {
        float s2  = (tid < 8) ? sh_s[tid]  : 0.f;
        float ss2 = (tid < 8) ? sh_ss[tid] : 0.f;
        #pragma unroll
        for (int o = 4; o > 0; o >>= 1) {
            s2  += __shfl_xor_sync(0xffffffffu, s2, o);
            ss2 += __shfl_xor_sync(0xffffffffu, ss2, o);
        }
        if (tid == 0) { sh_s[0] = s2; sh_ss[0] = ss2; }
    }
    __syncthreads();
    const float mean = sh_s[0] * (1.f / 65536.f);
    const float var  = sh_ss[0] * (1.f / 65536.f) - mean * mean;
    const float rstd = rsqrtf(var + 1e-5f);

    for (int i = tid; i < NG; i += 256) {
        int c = g * 64 + (i >> 10);
        int n = i & 1023;
        float v = (xb[i] - mean) * rstd;
        v = v * gamma[c] + beta[c];
        ht[(size_t)c * MCOLS + (size_t)b * NPIX + n] = v;
    }
}

// fp32 scores in -> half probabilities out
__global__ void softmax_kernel(const float* __restrict__ attn, __half* __restrict__ attnH) {
    const float* row = attn + (size_t)blockIdx.x * NPIX;
    __half* rowo = attnH + (size_t)blockIdx.x * NPIX;
    const int tid = threadIdx.x;
    float v[4];
    float mx = -1e30f;
    #pragma unroll
    for (int i = 0; i < 4; i++) {
        v[i] = row[tid + i * 256];
        mx = fmaxf(mx, v[i]);
    }
    #pragma unroll
    for (int o = 16; o > 0; o >>= 1)
        mx = fmaxf(mx, __shfl_xor_sync(0xffffffffu, mx, o));
    __shared__ float sh[8];
    if ((tid & 31) == 0) sh[tid >> 5] = mx;
    __syncthreads();
    if (tid < 32) {
        float m2 = (tid < 8) ? sh[tid] : -1e30f;
        #pragma unroll
        for (int o = 4; o > 0; o >>= 1)
            m2 = fmaxf(m2, __shfl_xor_sync(0xffffffffu, m2, o));
        if (tid == 0) sh[0] = m2;
    }
    __syncthreads();
    mx = sh[0];

    float s = 0.f;
    #pragma unroll
    for (int i = 0; i < 4; i++) {
        v[i] = __expf(v[i] - mx);
        s += v[i];
    }
    #pragma unroll
    for (int o = 16; o > 0; o >>= 1)
        s += __shfl_xor_sync(0xffffffffu, s, o);
    __shared__ float sh2[8];
    if ((tid & 31) == 0) sh2[tid >> 5] = s;
    __syncthreads();
    if (tid < 32) {
        float s2 = (tid < 8) ? sh2[tid] : 0.f;
        #pragma unroll
        for (int o = 4; o > 0; o >>= 1)
            s2 += __shfl_xor_sync(0xffffffffu, s2, o);
        if (tid == 0) sh2[0] = s2;
    }
    __syncthreads();
    const float inv = 1.f / sh2[0];
    #pragma unroll
    for (int i = 0; i < 4; i++) rowo[tid + i * 256] = __float2half(v[i] * inv);
}

// ---------------------------------------------------------------------------
// FP16 NT GEMM (fp32 accumulate), ldmatrix fragment loads:
//   D[bz, m, n] = alpha * sum_k A[m][k] * B[n][k] (+bias_m[m]) (+bias_n[n]) (+resid)
// Tile 128x256x64, 256 threads, 8 warps (2m x 4n), warp tile 64x64.
// 4-stage cp.async. M%128==0, N%256==0, K%64==0.
// ---------------------------------------------------------------------------
#define BM 128
#define BN 256
#define BKH 64
#define STAGES 4
#define LDAH 72                    // halves per smem row (64 + 8 pad)
#define A_STG_B (BM * LDAH * 2)    // 18432 bytes
#define B_STG_B (BN * LDAH * 2)    // 36864 bytes
#define SMEM_BYTES (STAGES * (A_STG_B + B_STG_B))   // 221184

__global__ __launch_bounds__(256, 1)
void hgemm(const __half* __restrict__ A, const __half* __restrict__ B,
           float* __restrict__ Cf, __half* __restrict__ Ch,
           const float* __restrict__ bias_m, const float* __restrict__ bias_n,
           const float* __restrict__ resid,
           int Kdim, long a_rs, long a_zs, long b_rs, long b_zs,
           long c_ms, long c_zs, float alpha) {
    extern __shared__ char smem_raw[];
    const uint32_t as_base = sm_u32(smem_raw);
    const uint32_t bs_base = as_base + STAGES * A_STG_B;

    const int tid = threadIdx.x, warp = tid >> 5, lane = tid & 31;
    const int gid = lane >> 2, tig = lane & 3;
    const int bx = blockIdx.x, by = blockIdx.y, bz = blockIdx.z;
    const int wm = (warp & 1) * 64;
    const int wn = (warp >> 1) * 64;
    const int lr = lane & 7, mi = lane >> 3;   // ldmatrix row / matrix index

    const __half* Ab = A + (size_t)bz * a_zs + (size_t)by * BM * a_rs;
    const __half* Bb = B + (size_t)bz * b_zs + (size_t)bx * BN * b_rs;

    float acc[4][8][4];
    #pragma unroll
    for (int i = 0; i < 4; i++)
        #pragma unroll
        for (int j = 0; j < 8; j++)
            #pragma unroll
            for (int r = 0; r < 4; r++) acc[i][j][r] = 0.f;

    auto fill = [&](int t) {
        const int s = t % STAGES;
        const __half* ag = Ab + (size_t)t * BKH;
        const uint32_t ad = as_base + s * A_STG_B;
        #pragma unroll
        for (int i = 0; i < 4; i++) {
            int idx = tid + i * 256;
            int r = idx >> 3, g = idx & 7;
            cp16(ad + (uint32_t)(r * (LDAH * 2) + g * 16), ag + (size_t)r * a_rs + g * 8);
        }
        const __half* bg = Bb + (size_t)t * BKH;
        const uint32_t bd = bs_base + s * B_STG_B;
        #pragma unroll
        for (int i = 0; i < 8; i++) {
            int idx = tid + i * 256;
            int r = idx >> 3, g = idx & 7;
            cp16(bd + (uint32_t)(r * (LDAH * 2) + g * 16), bg + (size_t)r * b_rs + g * 8);
        }
        asm volatile("cp.async.commit_group;" ::: "memory");
    };

    const int T = Kdim / BKH;
    fill(0);
    if (T > 1) fill(1);
    if (T > 2) fill(2);

    for (int t = 0; t < T; t++) {
        if (t + 3 <= T)      asm volatile("cp.async.wait_group 2;" ::: "memory");
        else if (t + 2 == T) asm volatile("cp.async.wait_group 1;" ::: "memory");
        else                 asm volatile("cp.async.wait_group 0;" ::: "memory");
        __syncthreads();

        if (t + 3 < T) fill(t + 3);

        const int s = t % STAGES;
        const uint32_t as_s = as_base + s * A_STG_B;
        const uint32_t bs_s = bs_base + s * B_STG_B;

        #pragma unroll
        for (int sl = 0; sl < 4; sl++) {        // k16 slices within BK=64
            const int kh = sl * 16;             // half offset of slice
            uint32_t af[4][4], bf[8][2];
            // A: x4 per i-tile; matrices (m0 klo)(m8 klo)(m0 khi)(m8 khi)
            #pragma unroll
            for (int i = 0; i < 4; i++) {
                uint32_t addr = as_s + 2u * (uint32_t)(
                    (wm + i * 16 + (mi & 1) * 8 + lr) * LDAH + kh + (mi >> 1) * 8);
                ldmx4(af[i], addr);
            }
            // B: x4 per j-pair; matrices (n0 klo)(n0 khi)(n8 klo)(n8 khi)
            #pragma unroll
            for (int j2 = 0; j2 < 4; j2++) {
                uint32_t r[4];
                uint32_t addr = bs_s + 2u * (uint32_t)(
                    (wn + j2 * 16 + (mi >> 1) * 8 + lr) * LDAH + kh + (mi & 1) * 8);
                ldmx4(r, addr);
                bf[j2 * 2][0] = r[0]; bf[j2 * 2][1] = r[1];
                bf[j2 * 2 + 1][0] = r[2]; bf[j2 * 2 + 1][1] = r[3];
            }
            #pragma unroll
            for (int i = 0; i < 4; i++)
                #pragma unroll
                for (int j = 0; j < 8; j++)
                    mma_f16(acc[i][j], af[i], bf[j]);
        }
    }

    // ---- epilogue ----
    #pragma unroll
    for (int i = 0; i < 4; i++) {
        const int m0 = by * BM + wm + i * 16 + gid;
        const float bv0 = bias_m ? bias_m[m0] : 0.f;
        const float bv1 = bias_m ? bias_m[m0 + 8] : 0.f;
        #pragma unroll
        for (int j = 0; j < 8; j++) {
            const int n0 = bx * BN + wn + j * 8 + tig * 2;
            const float bn0 = bias_n ? bias_n[n0] : 0.f;
            const float bn1 = bias_n ? bias_n[n0 + 1] : 0.f;
            size_t o0 = (size_t)bz * c_zs + (size_t)m0 * c_ms + n0;
            size_t o1 = o0 + 8 * c_ms;
            float v0 = acc[i][j][0] * alpha + bv0 + bn0;
            float v1 = acc[i][j][1] * alpha + bv0 + bn1;
            float v2 = acc[i][j][2] * alpha + bv1 + bn0;
            float v3 = acc[i][j][3] * alpha + bv1 + bn1;
            if (resid) {
                v0 += resid[o0]; v1 += resid[o0 + 1];
                v2 += resid[o1]; v3 += resid[o1 + 1];
            }
            if (Ch) {
                *(__half2*)(Ch + o0) = __floats2half2_rn(v0, v1);
                *(__half2*)(Ch + o1) = __floats2half2_rn(v2, v3);
            } else {
                *(float2*)(Cf + o0) = make_float2(v0, v1);
                *(float2*)(Cf + o1) = make_float2(v2, v3);
            }
        }
    }
}

// ---------------------------------------------------------------------------
// Launch
// ---------------------------------------------------------------------------
extern "C" void kernel_launch(void* const* d_in, const int* in_sizes, int n_in,
                              void* d_out, int out_size) {
    const float* x      = (const float*)d_in[0];
    const float* gamma  = (const float*)d_in[1];
    const float* beta   = (const float*)d_in[2];
    const float* w_qkv  = (const float*)d_in[3];
    const float* b_qkv  = (const float*)d_in[4];
    const float* w_proj = (const float*)d_in[5];
    const float* b_proj = (const float*)d_in[6];
    float* out = (float*)d_out;

    float *ht, *attn;
    __half *hT, *wqkvH, *wprojH, *qkvT, *attnH, *vC, *obT;
    cudaGetSymbolAddress((void**)&ht,     g_ht);
    cudaGetSymbolAddress((void**)&hT,     g_hT);
    cudaGetSymbolAddress((void**)&wqkvH,  g_wqkvH);
    cudaGetSymbolAddress((void**)&wprojH, g_wprojH);
    cudaGetSymbolAddress((void**)&qkvT,   g_qkvT);
    cudaGetSymbolAddress((void**)&attn,   g_attn);
    cudaGetSymbolAddress((void**)&attnH,  g_attnH);
    cudaGetSymbolAddress((void**)&vC,     g_vC);
    cudaGetSymbolAddress((void**)&obT,    g_obT);

    cudaFuncSetAttribute(hgemm, cudaFuncAttributeMaxDynamicSharedMemorySize, SMEM_BYTES);

    const float scale = 1.0f / sqrtf((float)CDIM);

    // 0) convert weights to half ([o][c] is already the NT B operand)
    convert_h_kernel<<<(3 * CDIM * CDIM) / 256, 256>>>(w_qkv, wqkvH, 3 * CDIM * CDIM);
    convert_h_kernel<<<(CDIM * CDIM) / 256, 256>>>(w_proj, wprojH, CDIM * CDIM);

    // 1) GroupNorm -> ht[c][t] fp32
    groupnorm_kernel<<<BATCH * 8, 256>>>(x, gamma, beta, ht);

    // 2) ht[c][t] -> hT[t][c] half
    transpose_f2h<<<dim3(MCOLS / 32, CDIM / 32), 256>>>(ht, hT, CDIM, MCOLS);

    // 3) QKV: qkvT[t][o] = sum_c hT[t][c] * wqkvH[o][c] + b_qkv[o]
    hgemm<<<dim3(1536 / BN, MCOLS / BM, 1), 256, SMEM_BYTES>>>(
        hT, wqkvH, nullptr, qkvT, nullptr, b_qkv, nullptr,
        CDIM, /*a_rs*/ CDIM, 0, /*b_rs*/ CDIM, 0,
        /*c_ms*/ 1536, 0, 1.0f);

    // 4) Scores: attn[b][i][j] = scale * sum_c q[i][c] * k[j][c]
    hgemm<<<dim3(NPIX / BN, NPIX / BM, BATCH), 256, SMEM_BYTES>>>(
        qkvT, qkvT + 512, attn, nullptr, nullptr, nullptr, nullptr,
        CDIM, /*a_rs*/ 1536, /*a_zs*/ (long)NPIX * 1536,
        /*b_rs*/ 1536, /*b_zs*/ (long)NPIX * 1536,
        /*c_ms*/ NPIX, (long)NPIX * NPIX, scale);

    // 5) Softmax fp32 -> half probs
    softmax_kernel<<<BATCH * NPIX, 256>>>(attn, attnH);

    // 6) v part of qkvT [t][1024+c] -> vC[c][t]
    transpose_h2h<<<dim3(CDIM / 32, MCOLS / 32), 256>>>(
        qkvT + 1024, vC, MCOLS, /*in_rs*/ 1536, /*out_rs*/ MCOLS);

    // 7) PV: obT[b*1024+i][c] = sum_j attnH[b][i][j] * vC[c][b*1024+j]
    hgemm<<<dim3(CDIM / BN, NPIX / BM, BATCH), 256, SMEM_BYTES>>>(
        attnH, vC, nullptr, obT, nullptr, nullptr, nullptr,
        NPIX, /*a_rs*/ NPIX, /*a_zs*/ (long)NPIX * NPIX,
        /*b_rs*/ MCOLS, /*b_zs*/ (long)NPIX,
        /*c_ms*/ CDIM, (long)NPIX * CDIM, 1.0f);

    // 8) Proj: out[b][o][n] = sum_c wprojH[o][c] * obT[b*1024+n][c] + b_proj[o] + x
    hgemm<<<dim3(NPIX / BN, CDIM / BM, BATCH), 256, SMEM_BYTES>>>(
        wprojH, obT, out, nullptr, b_proj, nullptr, x,
        CDIM, /*a_rs*/ CDIM, 0, /*b_rs*/ CDIM, /*b_zs*/ (long)NPIX * CDIM,
        /*c_ms*/ NPIX, (long)CDIM * NPIX, 1.0f);
}

// round 9
// speedup vs baseline: 3.2336x; 1.0919x over previous
#include <cuda_runtime.h>
#include <cuda_fp16.h>
#include <math.h>
#include <stdint.h>

#define CDIM 512
#define BATCH 16
#define NPIX 1024
#define MCOLS (BATCH * NPIX)   // 16384

// ---------------------------------------------------------------------------
// Scratch (device globals)
// ---------------------------------------------------------------------------
__device__ float  g_stats [BATCH * 8 * 2];                 // mean, rstd per (b,g)
__device__ __half g_hT    [(size_t)MCOLS * CDIM];          // [t][c]
__device__ __half g_wqkvH [(size_t)3 * CDIM * CDIM];       // [o][c]
__device__ __half g_wprojH[(size_t)CDIM * CDIM];           // [o][c]
__device__ __half g_qkvT  [(size_t)MCOLS * 3 * CDIM];      // [t][o]  q|k|v
__device__ float  g_attn  [(size_t)BATCH * NPIX * NPIX];   // [b][i][j] fp32 scores
__device__ __half g_attnH [(size_t)BATCH * NPIX * NPIX];   // [b][i][j] softmaxed
__device__ __half g_vC    [(size_t)CDIM * MCOLS];          // [c][t]
__device__ __half g_obT   [(size_t)MCOLS * CDIM];          // [t][c]

// ---------------------------------------------------------------------------
// Helpers
// ---------------------------------------------------------------------------
__device__ __forceinline__ uint32_t sm_u32(const void* p) {
    uint32_t a;
    asm("{ .reg .u64 t; cvta.to.shared.u64 t, %1; cvt.u32.u64 %0, t; }" : "=r"(a) : "l"(p));
    return a;
}
__device__ __forceinline__ void cp16(uint32_t dst, const void* src) {
    asm volatile("cp.async.cg.shared.global [%0], [%1], 16;" :: "r"(dst), "l"(src));
}
__device__ __forceinline__ void mma_f16(float c[4], const uint32_t a[4],
                                        const uint32_t b[2]) {
    asm volatile(
        "mma.sync.aligned.m16n8k16.row.col.f32.f16.f16.f32 "
        "{%0,%1,%2,%3}, {%4,%5,%6,%7}, {%8,%9}, {%0,%1,%2,%3};\n"
        : "+f"(c[0]), "+f"(c[1]), "+f"(c[2]), "+f"(c[3])
        : "r"(a[0]), "r"(a[1]), "r"(a[2]), "r"(a[3]), "r"(b[0]), "r"(b[1]));
}
__device__ __forceinline__ void ldmx4(uint32_t r[4], uint32_t addr) {
    asm volatile("ldmatrix.sync.aligned.m8n8.x4.shared.b16 {%0,%1,%2,%3}, [%4];"
                 : "=r"(r[0]), "=r"(r[1]), "=r"(r[2]), "=r"(r[3]) : "r"(addr));
}

// ---------------------------------------------------------------------------
// Small kernels
// ---------------------------------------------------------------------------
__global__ void convert_h_kernel(const float* __restrict__ in, __half* __restrict__ out, int n) {
    int i = blockIdx.x * 256 + threadIdx.x;
    if (i < n) out[i] = __float2half(in[i]);
}

// GroupNorm stats: one block per (b, g); writes mean, rstd
__global__ void gn_stats_kernel(const float* __restrict__ x, float* __restrict__ stats) {
    const int b = blockIdx.x >> 3;
    const int g = blockIdx.x & 7;
    const float* xb = x + ((size_t)b * CDIM + (size_t)g * 64) * NPIX;
    const int tid = threadIdx.x;
    const int NG = 64 * NPIX;

    float s = 0.f, ss = 0.f;
    for (int i = tid; i < NG; i += 256) {
        float v = xb[i];
        s += v; ss += v * v;
    }
    #pragma unroll
    for (int o = 16; o > 0; o >>= 1) {
        s  += __shfl_xor_sync(0xffffffffu, s, o);
        ss += __shfl_xor_sync(0xffffffffu, ss, o);
    }
    __shared__ float sh_s[8], sh_ss[8];
    if ((tid & 31) == 0) { sh_s[tid >> 5] = s; sh_ss[tid >> 5] = ss; }
    __syncthreads();
    if (tid == 0) {
        float s2 = 0.f, ss2 = 0.f;
        #pragma unroll
        for (int i = 0; i < 8; i++) { s2 += sh_s[i]; ss2 += sh_ss[i]; }
        const float mean = s2 * (1.f / 65536.f);
        const float var  = ss2 * (1.f / 65536.f) - mean * mean;
        stats[blockIdx.x * 2 + 0] = mean;
        stats[blockIdx.x * 2 + 1] = rsqrtf(var + 1e-5f);
    }
}

// Fused normalize + transpose: x[b][c][n] -> hT[b*1024+n][c] (half)
// grid: (C/32, NPIX/32, BATCH)
__global__ void gn_apply_T(const float* __restrict__ x, const float* __restrict__ stats,
                           const float* __restrict__ gamma, const float* __restrict__ beta,
                           __half* __restrict__ hT) {
    __shared__ float t[32][33];
    const int b = blockIdx.z;
    const int tx = threadIdx.x & 31, ty = threadIdx.x >> 5;
    const int c0 = blockIdx.x * 32, n0 = blockIdx.y * 32;
    const float* xb = x + (size_t)b * CDIM * NPIX;
    #pragma unroll
    for (int k = 0; k < 4; k++) {
        const int c = c0 + ty + 8 * k;
        const float mean = stats[(b * 8 + (c >> 6)) * 2 + 0];
        const float rstd = stats[(b * 8 + (c >> 6)) * 2 + 1];
        float v = xb[(size_t)c * NPIX + n0 + tx];
        t[ty + 8 * k][tx] = (v - mean) * rstd * gamma[c] + beta[c];
    }
    __syncthreads();
    #pragma unroll
    for (int k = 0; k < 4; k++) {
        const int n = n0 + ty + 8 * k;
        hT[(size_t)(b * NPIX + n) * CDIM + c0 + tx] = __float2half(t[tx][ty + 8 * k]);
    }
}

// in rows R x cols C (row stride in_rs, half) -> out[C][R] (row stride out_rs)
__global__ void transpose_h2h(const __half* __restrict__ in, __half* __restrict__ out,
                              int R, long in_rs, long out_rs) {
    __shared__ __half t[32][34];
    const int tx = threadIdx.x & 31, ty = threadIdx.x >> 5;
    const int r0 = blockIdx.y * 32, c0 = blockIdx.x * 32;
    #pragma unroll
    for (int k = 0; k < 4; k++)
        t[ty + 8 * k][tx] = in[(size_t)(r0 + ty + 8 * k) * in_rs + c0 + tx];
    __syncthreads();
    #pragma unroll
    for (int k = 0; k < 4; k++)
        out[(size_t)(c0 + ty + 8 * k) * out_rs + r0 + tx] = t[tx][ty + 8 * k];
}

// fp32 scores in -> half probabilities out
__global__ void softmax_kernel(const float* __restrict__ attn, __half* __restrict__ attnH) {
    const float* row = attn + (size_t)blockIdx.x * NPIX;
    __half* rowo = attnH + (size_t)blockIdx.x * NPIX;
    const int tid = threadIdx.x;
    float v[4];
    float mx = -1e30f;
    #pragma unroll
    for (int i = 0; i < 4; i++) {
        v[i] = row[tid + i * 256];
        mx = fmaxf(mx, v[i]);
    }
    #pragma unroll
    for (int o = 16; o > 0; o >>= 1)
        mx = fmaxf(mx, __shfl_xor_sync(0xffffffffu, mx, o));
    __shared__ float sh[8];
    if ((tid & 31) == 0) sh[tid >> 5] = mx;
    __syncthreads();
    if (tid < 32) {
        float m2 = (tid < 8) ? sh[tid] : -1e30f;
        #pragma unroll
        for (int o = 4; o > 0; o >>= 1)
            m2 = fmaxf(m2, __shfl_xor_sync(0xffffffffu, m2, o));
        if (tid == 0) sh[0] = m2;
    }
    __syncthreads();
    mx = sh[0];

    float s = 0.f;
    #pragma unroll
    for (int i = 0; i < 4; i++) {
        v[i] = __expf(v[i] - mx);
        s += v[i];
    }
    #pragma unroll
    for (int o = 16; o > 0; o >>= 1)
        s += __shfl_xor_sync(0xffffffffu, s, o);
    __shared__ float sh2[8];
    if ((tid & 31) == 0) sh2[tid >> 5] = s;
    __syncthreads();
    if (tid < 32) {
        float s2 = (tid < 8) ? sh2[tid] : 0.f;
        #pragma unroll
        for (int o = 4; o > 0; o >>= 1)
            s2 += __shfl_xor_sync(0xffffffffu, s2, o);
        if (tid == 0) sh2[0] = s2;
    }
    __syncthreads();
    const float inv = 1.f / sh2[0];
    #pragma unroll
    for (int i = 0; i < 4; i++) rowo[tid + i * 256] = __float2half(v[i] * inv);
}

// ---------------------------------------------------------------------------
// FP16 NT GEMM (fp32 accumulate), ldmatrix fragment loads:
//   D[bz, m, n] = alpha * sum_k A[m][k] * B[n][k] (+bias_m[m]) (+bias_n[n]) (+resid)
// Tile 128x128x64, 256 threads, 8 warps (2m x 4n), warp tile 64x32.
// 3-stage cp.async, 2 CTAs/SM. M%128==0, N%128==0, K%64==0.
// ---------------------------------------------------------------------------
#define BM 128
#define BN 128
#define BKH 64
#define STAGES 3
#define LDAH 72                    // halves per smem row (64 + 8 pad)
#define A_STG_B (BM * LDAH * 2)    // 18432 bytes
#define B_STG_B (BN * LDAH * 2)    // 18432 bytes
#define SMEM_BYTES (STAGES * (A_STG_B + B_STG_B))   // 110592

__global__ __launch_bounds__(256, 2)
void hgemm(const __half* __restrict__ A, const __half* __restrict__ B,
           float* __restrict__ Cf, __half* __restrict__ Ch,
           const float* __restrict__ bias_m, const float* __restrict__ bias_n,
           const float* __restrict__ resid,
           int Kdim, long a_rs, long a_zs, long b_rs, long b_zs,
           long c_ms, long c_zs, float alpha) {
    extern __shared__ char smem_raw[];
    const uint32_t as_base = sm_u32(smem_raw);
    const uint32_t bs_base = as_base + STAGES * A_STG_B;

    const int tid = threadIdx.x, warp = tid >> 5, lane = tid & 31;
    const int gid = lane >> 2, tig = lane & 3;
    const int bx = blockIdx.x, by = blockIdx.y, bz = blockIdx.z;
    const int wm = (warp & 1) * 64;
    const int wn = (warp >> 1) * 32;
    const int lr = lane & 7, mi = lane >> 3;   // ldmatrix row / matrix index

    const __half* Ab = A + (size_t)bz * a_zs + (size_t)by * BM * a_rs;
    const __half* Bb = B + (size_t)bz * b_zs + (size_t)bx * BN * b_rs;

    float acc[4][4][4];
    #pragma unroll
    for (int i = 0; i < 4; i++)
        #pragma unroll
        for (int j = 0; j < 4; j++)
            #pragma unroll
            for (int r = 0; r < 4; r++) acc[i][j][r] = 0.f;

    auto fill = [&](int t) {
        const int s = t % STAGES;
        const __half* ag = Ab + (size_t)t * BKH;
        const uint32_t ad = as_base + s * A_STG_B;
        #pragma unroll
        for (int i = 0; i < 4; i++) {
            int idx = tid + i * 256;
            int r = idx >> 3, g = idx & 7;
            cp16(ad + (uint32_t)(r * (LDAH * 2) + g * 16), ag + (size_t)r * a_rs + g * 8);
        }
        const __half* bg = Bb + (size_t)t * BKH;
        const uint32_t bd = bs_base + s * B_STG_B;
        #pragma unroll
        for (int i = 0; i < 4; i++) {
            int idx = tid + i * 256;
            int r = idx >> 3, g = idx & 7;
            cp16(bd + (uint32_t)(r * (LDAH * 2) + g * 16), bg + (size_t)r * b_rs + g * 8);
        }
        asm volatile("cp.async.commit_group;" ::: "memory");
    };

    const int T = Kdim / BKH;
    fill(0);
    if (T > 1) fill(1);

    for (int t = 0; t < T; t++) {
        if (t < T - 1) asm volatile("cp.async.wait_group 1;" ::: "memory");
        else           asm volatile("cp.async.wait_group 0;" ::: "memory");
        __syncthreads();

        if (t + 2 < T) fill(t + 2);

        const int s = t % STAGES;
        const uint32_t as_s = as_base + s * A_STG_B;
        const uint32_t bs_s = bs_base + s * B_STG_B;

        #pragma unroll
        for (int sl = 0; sl < 4; sl++) {        // k16 slices within BK=64
            const int kh = sl * 16;
            uint32_t af[4][4], bf[4][2];
            // A: x4 per i-tile; matrices (m0 klo)(m8 klo)(m0 khi)(m8 khi)
            #pragma unroll
            for (int i = 0; i < 4; i++) {
                uint32_t addr = as_s + 2u * (uint32_t)(
                    (wm + i * 16 + (mi & 1) * 8 + lr) * LDAH + kh + (mi >> 1) * 8);
                ldmx4(af[i], addr);
            }
            // B: x4 per j-pair; matrices (n0 klo)(n0 khi)(n8 klo)(n8 khi)
            #pragma unroll
            for (int j2 = 0; j2 < 2; j2++) {
                uint32_t r[4];
                uint32_t addr = bs_s + 2u * (uint32_t)(
                    (wn + j2 * 16 + (mi >> 1) * 8 + lr) * LDAH + kh + (mi & 1) * 8);
                ldmx4(r, addr);
                bf[j2 * 2][0] = r[0]; bf[j2 * 2][1] = r[1];
                bf[j2 * 2 + 1][0] = r[2]; bf[j2 * 2 + 1][1] = r[3];
            }
            #pragma unroll
            for (int i = 0; i < 4; i++)
                #pragma unroll
                for (int j = 0; j < 4; j++)
                    mma_f16(acc[i][j], af[i], bf[j]);
        }
    }

    // ---- epilogue ----
    #pragma unroll
    for (int i = 0; i < 4; i++) {
        const int m0 = by * BM + wm + i * 16 + gid;
        const float bv0 = bias_m ? bias_m[m0] : 0.f;
        const float bv1 = bias_m ? bias_m[m0 + 8] : 0.f;
        #pragma unroll
        for (int j = 0; j < 4; j++) {
            const int n0 = bx * BN + wn + j * 8 + tig * 2;
            const float bn0 = bias_n ? bias_n[n0] : 0.f;
            const float bn1 = bias_n ? bias_n[n0 + 1] : 0.f;
            size_t o0 = (size_t)bz * c_zs + (size_t)m0 * c_ms + n0;
            size_t o1 = o0 + 8 * c_ms;
            float v0 = acc[i][j][0] * alpha + bv0 + bn0;
            float v1 = acc[i][j][1] * alpha + bv0 + bn1;
            float v2 = acc[i][j][2] * alpha + bv1 + bn0;
            float v3 = acc[i][j][3] * alpha + bv1 + bn1;
            if (resid) {
                v0 += resid[o0]; v1 += resid[o0 + 1];
                v2 += resid[o1]; v3 += resid[o1 + 1];
            }
            if (Ch) {
                *(__half2*)(Ch + o0) = __floats2half2_rn(v0, v1);
                *(__half2*)(Ch + o1) = __floats2half2_rn(v2, v3);
            } else {
                *(float2*)(Cf + o0) = make_float2(v0, v1);
                *(float2*)(Cf + o1) = make_float2(v2, v3);
            }
        }
    }
}

// ---------------------------------------------------------------------------
// Launch
// ---------------------------------------------------------------------------
extern "C" void kernel_launch(void* const* d_in, const int* in_sizes, int n_in,
                              void* d_out, int out_size) {
    const float* x      = (const float*)d_in[0];
    const float* gamma  = (const float*)d_in[1];
    const float* beta   = (const float*)d_in[2];
    const float* w_qkv  = (const float*)d_in[3];
    const float* b_qkv  = (const float*)d_in[4];
    const float* w_proj = (const float*)d_in[5];
    const float* b_proj = (const float*)d_in[6];
    float* out = (float*)d_out;

    float *stats, *attn;
    __half *hT, *wqkvH, *wprojH, *qkvT, *attnH, *vC, *obT;
    cudaGetSymbolAddress((void**)&stats,  g_stats);
    cudaGetSymbolAddress((void**)&hT,     g_hT);
    cudaGetSymbolAddress((void**)&wqkvH,  g_wqkvH);
    cudaGetSymbolAddress((void**)&wprojH, g_wprojH);
    cudaGetSymbolAddress((void**)&qkvT,   g_qkvT);
    cudaGetSymbolAddress((void**)&attn,   g_attn);
    cudaGetSymbolAddress((void**)&attnH,  g_attnH);
    cudaGetSymbolAddress((void**)&vC,     g_vC);
    cudaGetSymbolAddress((void**)&obT,    g_obT);

    cudaFuncSetAttribute(hgemm, cudaFuncAttributeMaxDynamicSharedMemorySize, SMEM_BYTES);

    const float scale = 1.0f / sqrtf((float)CDIM);

    // 0) convert weights to half ([o][c] is already the NT B operand)
    convert_h_kernel<<<(3 * CDIM * CDIM) / 256, 256>>>(w_qkv, wqkvH, 3 * CDIM * CDIM);
    convert_h_kernel<<<(CDIM * CDIM) / 256, 256>>>(w_proj, wprojH, CDIM * CDIM);

    // 1) GroupNorm stats, then fused normalize+transpose -> hT[t][c] half
    gn_stats_kernel<<<BATCH * 8, 256>>>(x, stats);
    gn_apply_T<<<dim3(CDIM / 32, NPIX / 32, BATCH), 256>>>(x, stats, gamma, beta, hT);

    // 2) QKV: qkvT[t][o] = sum_c hT[t][c] * wqkvH[o][c] + b_qkv[o]
    hgemm<<<dim3(1536 / BN, MCOLS / BM, 1), 256, SMEM_BYTES>>>(
        hT, wqkvH, nullptr, qkvT, nullptr, b_qkv, nullptr,
        CDIM, /*a_rs*/ CDIM, 0, /*b_rs*/ CDIM, 0,
        /*c_ms*/ 1536, 0, 1.0f);

    // 3) Scores: attn[b][i][j] = scale * sum_c q[i][c] * k[j][c]
    hgemm<<<dim3(NPIX / BN, NPIX / BM, BATCH), 256, SMEM_BYTES>>>(
        qkvT, qkvT + 512, attn, nullptr, nullptr, nullptr, nullptr,
        CDIM, /*a_rs*/ 1536, /*a_zs*/ (long)NPIX * 1536,
        /*b_rs*/ 1536, /*b_zs*/ (long)NPIX * 1536,
        /*c_ms*/ NPIX, (long)NPIX * NPIX, scale);

    // 4) Softmax fp32 -> half probs
    softmax_kernel<<<BATCH * NPIX, 256>>>(attn, attnH);

    // 5) v part of qkvT [t][1024+c] -> vC[c][t]
    transpose_h2h<<<dim3(CDIM / 32, MCOLS / 32), 256>>>(
        qkvT + 1024, vC, MCOLS, /*in_rs*/ 1536, /*out_rs*/ MCOLS);

    // 6) PV: obT[b*1024+i][c] = sum_j attnH[b][i][j] * vC[c][b*1024+j]
    hgemm<<<dim3(CDIM / BN, NPIX / BM, BATCH), 256, SMEM_BYTES>>>(
        attnH, vC, nullptr, obT, nullptr, nullptr, nullptr,
        NPIX, /*a_rs*/ NPIX, /*a_zs*/ (long)NPIX * NPIX,
        /*b_rs*/ MCOLS, /*b_zs*/ (long)NPIX,
        /*c_ms*/ CDIM, (long)NPIX * CDIM, 1.0f);

    // 7) Proj: out[b][o][n] = sum_c wprojH[o][c] * obT[b*1024+n][c] + b_proj[o] + x
    hgemm<<<dim3(NPIX / BN, CDIM / BM, BATCH), 256, SMEM_BYTES>>>(
        wprojH, obT, out, nullptr, b_proj, nullptr, x,
        CDIM, /*a_rs*/ CDIM, 0, /*b_rs*/ CDIM, /*b_zs*/ (long)NPIX * CDIM,
        /*c_ms*/ NPIX, (long)CDIM * NPIX, 1.0f);
}

// round 10
// speedup vs baseline: 3.4896x; 1.0792x over previous
#include <cuda_runtime.h>
#include <cuda_fp16.h>
#include <math.h>
#include <stdint.h>

#define CDIM 512
#define BATCH 16
#define NPIX 1024
#define MCOLS (BATCH * NPIX)   // 16384

// ---------------------------------------------------------------------------
// Scratch (device globals)
// ---------------------------------------------------------------------------
__device__ float  g_stats [BATCH * 8 * 2];                 // mean, rstd per (b,g)
__device__ __half g_hT    [(size_t)MCOLS * CDIM];          // [t][c]
__device__ __half g_wqkvH [(size_t)3 * CDIM * CDIM];       // [o][c]
__device__ __half g_wprojH[(size_t)CDIM * CDIM];           // [o][c]
__device__ __half g_qkvT  [(size_t)MCOLS * 3 * CDIM];      // [t][o]  q|k|v
__device__ __half g_attnH [(size_t)BATCH * NPIX * NPIX];   // [b][i][j] scores -> probs
__device__ __half g_obT   [(size_t)MCOLS * CDIM];          // [t][c]

// ---------------------------------------------------------------------------
// Helpers
// ---------------------------------------------------------------------------
__device__ __forceinline__ uint32_t sm_u32(const void* p) {
    uint32_t a;
    asm("{ .reg .u64 t; cvta.to.shared.u64 t, %1; cvt.u32.u64 %0, t; }" : "=r"(a) : "l"(p));
    return a;
}
__device__ __forceinline__ void cp16(uint32_t dst, const void* src) {
    asm volatile("cp.async.cg.shared.global [%0], [%1], 16;" :: "r"(dst), "l"(src));
}
__device__ __forceinline__ void mma_f16(float c[4], const uint32_t a[4],
                                        const uint32_t b[2]) {
    asm volatile(
        "mma.sync.aligned.m16n8k16.row.col.f32.f16.f16.f32 "
        "{%0,%1,%2,%3}, {%4,%5,%6,%7}, {%8,%9}, {%0,%1,%2,%3};\n"
        : "+f"(c[0]), "+f"(c[1]), "+f"(c[2]), "+f"(c[3])
        : "r"(a[0]), "r"(a[1]), "r"(a[2]), "r"(a[3]), "r"(b[0]), "r"(b[1]));
}
__device__ __forceinline__ void ldmx4(uint32_t r[4], uint32_t addr) {
    asm volatile("ldmatrix.sync.aligned.m8n8.x4.shared.b16 {%0,%1,%2,%3}, [%4];"
                 : "=r"(r[0]), "=r"(r[1]), "=r"(r[2]), "=r"(r[3]) : "r"(addr));
}
__device__ __forceinline__ void ldmx4t(uint32_t r[4], uint32_t addr) {
    asm volatile("ldmatrix.sync.aligned.m8n8.x4.trans.shared.b16 {%0,%1,%2,%3}, [%4];"
                 : "=r"(r[0]), "=r"(r[1]), "=r"(r[2]), "=r"(r[3]) : "r"(addr));
}

// ---------------------------------------------------------------------------
// Small kernels
// ---------------------------------------------------------------------------
__global__ void convert_h_kernel(const float* __restrict__ in, __half* __restrict__ out, int n) {
    int i = blockIdx.x * 256 + threadIdx.x;
    if (i < n) out[i] = __float2half(in[i]);
}

// GroupNorm stats: one block per (b, g); writes mean, rstd
__global__ void gn_stats_kernel(const float* __restrict__ x, float* __restrict__ stats) {
    const int b = blockIdx.x >> 3;
    const int g = blockIdx.x & 7;
    const float4* xb = (const float4*)(x + ((size_t)b * CDIM + (size_t)g * 64) * NPIX);
    const int tid = threadIdx.x;
    const int NG4 = 64 * NPIX / 4;   // 16384 float4

    float s = 0.f, ss = 0.f;
    for (int i = tid; i < NG4; i += 256) {
        float4 v = xb[i];
        s  += v.x + v.y + v.z + v.w;
        ss += v.x * v.x + v.y * v.y + v.z * v.z + v.w * v.w;
    }
    #pragma unroll
    for (int o = 16; o > 0; o >>= 1) {
        s  += __shfl_xor_sync(0xffffffffu, s, o);
        ss += __shfl_xor_sync(0xffffffffu, ss, o);
    }
    __shared__ float sh_s[8], sh_ss[8];
    if ((tid & 31) == 0) { sh_s[tid >> 5] = s; sh_ss[tid >> 5] = ss; }
    __syncthreads();
    if (tid == 0) {
        float s2 = 0.f, ss2 = 0.f;
        #pragma unroll
        for (int i = 0; i < 8; i++) { s2 += sh_s[i]; ss2 += sh_ss[i]; }
        const float mean = s2 * (1.f / 65536.f);
        const float var  = ss2 * (1.f / 65536.f) - mean * mean;
        stats[blockIdx.x * 2 + 0] = mean;
        stats[blockIdx.x * 2 + 1] = rsqrtf(var + 1e-5f);
    }
}

// Fused normalize + transpose: x[b][c][n] -> hT[b*1024+n][c] (half)
__global__ void gn_apply_T(const float* __restrict__ x, const float* __restrict__ stats,
                           const float* __restrict__ gamma, const float* __restrict__ beta,
                           __half* __restrict__ hT) {
    __shared__ float t[32][33];
    const int b = blockIdx.z;
    const int tx = threadIdx.x & 31, ty = threadIdx.x >> 5;
    const int c0 = blockIdx.x * 32, n0 = blockIdx.y * 32;
    const float* xb = x + (size_t)b * CDIM * NPIX;
    #pragma unroll
    for (int k = 0; k < 4; k++) {
        const int c = c0 + ty + 8 * k;
        const float mean = stats[(b * 8 + (c >> 6)) * 2 + 0];
        const float rstd = stats[(b * 8 + (c >> 6)) * 2 + 1];
        float v = xb[(size_t)c * NPIX + n0 + tx];
        t[ty + 8 * k][tx] = (v - mean) * rstd * gamma[c] + beta[c];
    }
    __syncthreads();
    #pragma unroll
    for (int k = 0; k < 4; k++) {
        const int n = n0 + ty + 8 * k;
        hT[(size_t)(b * NPIX + n) * CDIM + c0 + tx] = __float2half(t[tx][ty + 8 * k]);
    }
}

// in-place softmax over half rows of length NPIX
__global__ void softmax_kernel(__half* __restrict__ attnH) {
    __half* row = attnH + (size_t)blockIdx.x * NPIX;
    const int tid = threadIdx.x;
    float v[4];
    float mx = -1e30f;
    #pragma unroll
    for (int i = 0; i < 2; i++) {
        __half2 h = *(__half2*)(row + tid * 2 + i * 512);
        float2 f = __half22float2(h);
        v[i * 2] = f.x; v[i * 2 + 1] = f.y;
        mx = fmaxf(mx, fmaxf(f.x, f.y));
    }
    #pragma unroll
    for (int o = 16; o > 0; o >>= 1)
        mx = fmaxf(mx, __shfl_xor_sync(0xffffffffu, mx, o));
    __shared__ float sh[8];
    if ((tid & 31) == 0) sh[tid >> 5] = mx;
    __syncthreads();
    if (tid < 32) {
        float m2 = (tid < 8) ? sh[tid] : -1e30f;
        #pragma unroll
        for (int o = 4; o > 0; o >>= 1)
            m2 = fmaxf(m2, __shfl_xor_sync(0xffffffffu, m2, o));
        if (tid == 0) sh[0] = m2;
    }
    __syncthreads();
    mx = sh[0];

    float s = 0.f;
    #pragma unroll
    for (int i = 0; i < 4; i++) {
        v[i] = __expf(v[i] - mx);
        s += v[i];
    }
    #pragma unroll
    for (int o = 16; o > 0; o >>= 1)
        s += __shfl_xor_sync(0xffffffffu, s, o);
    __shared__ float sh2[8];
    if ((tid & 31) == 0) sh2[tid >> 5] = s;
    __syncthreads();
    if (tid < 32) {
        float s2 = (tid < 8) ? sh2[tid] : 0.f;
        #pragma unroll
        for (int o = 4; o > 0; o >>= 1)
            s2 += __shfl_xor_sync(0xffffffffu, s2, o);
        if (tid == 0) sh2[0] = s2;
    }
    __syncthreads();
    const float inv = 1.f / sh2[0];
    #pragma unroll
    for (int i = 0; i < 2; i++)
        *(__half2*)(row + tid * 2 + i * 512) =
            __floats2half2_rn(v[i * 2] * inv, v[i * 2 + 1] * inv);
}

// ---------------------------------------------------------------------------
// FP16 GEMM (fp32 accumulate), ldmatrix fragment loads.
//   D[bz, m, n] = alpha * sum_k A[m][k] * B_k_n (+bias_m[m]) (+bias_n[n]) (+resid)
// A: [M rows][K] k-contiguous half, row stride a_rs.
// BT=0: B is [N rows][K] k-contiguous (NT).  BT=1: B is [K rows][N] n-contiguous
//       (row stride b_rs), loaded via ldmatrix.trans.
// Tile 128x128x64, 256 threads, 8 warps (2m x 4n), warp tile 64x32.
// 3-stage cp.async, 2 CTAs/SM.
// ---------------------------------------------------------------------------
#define BM 128
#define BN 128
#define BKH 64
#define STAGES 3
#define LDAH 72                     // halves per A smem row (64 + 8 pad)
#define LDBT 136                    // halves per trans-B smem row (128 + 8 pad)
#define A_STG_B (BM * LDAH * 2)     // 18432 bytes
#define B_STG_N (BN * LDAH * 2)     // 18432 bytes (BT=0)
#define B_STG_T (BKH * LDBT * 2)    // 17408 bytes (BT=1)
#define SMEM_N (STAGES * (A_STG_B + B_STG_N))   // 110592
#define SMEM_T (STAGES * (A_STG_B + B_STG_T))   // 107520

template <int BT>
__global__ __launch_bounds__(256, 2)
void hgemm(const __half* __restrict__ A, const __half* __restrict__ B,
           float* __restrict__ Cf, __half* __restrict__ Ch,
           const float* __restrict__ bias_m, const float* __restrict__ bias_n,
           const float* __restrict__ resid,
           int Kdim, long a_rs, long a_zs, long b_rs, long b_zs,
           long c_ms, long c_zs, float alpha) {
    extern __shared__ char smem_raw[];
    const uint32_t as_base = sm_u32(smem_raw);
    const uint32_t bs_base = as_base + STAGES * A_STG_B;
    const int BSTG = BT ? B_STG_T : B_STG_N;

    const int tid = threadIdx.x, warp = tid >> 5, lane = tid & 31;
    const int gid = lane >> 2, tig = lane & 3;
    const int bx = blockIdx.x, by = blockIdx.y, bz = blockIdx.z;
    const int wm = (warp & 1) * 64;
    const int wn = (warp >> 1) * 32;
    const int lr = lane & 7, mi = lane >> 3;

    const __half* Ab = A + (size_t)bz * a_zs + (size_t)by * BM * a_rs;
    const __half* Bb = BT ? (B + (size_t)bz * b_zs + (size_t)bx * BN)
                          : (B + (size_t)bz * b_zs + (size_t)bx * BN * b_rs);

    float acc[4][4][4];
    #pragma unroll
    for (int i = 0; i < 4; i++)
        #pragma unroll
        for (int j = 0; j < 4; j++)
            #pragma unroll
            for (int r = 0; r < 4; r++) acc[i][j][r] = 0.f;

    auto fill = [&](int t) {
        const int s = t % STAGES;
        const __half* ag = Ab + (size_t)t * BKH;
        const uint32_t ad = as_base + s * A_STG_B;
        #pragma unroll
        for (int i = 0; i < 4; i++) {
            int idx = tid + i * 256;
            int r = idx >> 3, g = idx & 7;
            cp16(ad + (uint32_t)(r * (LDAH * 2) + g * 16), ag + (size_t)r * a_rs + g * 8);
        }
        const uint32_t bd = bs_base + s * BSTG;
        if (BT) {
            // stage [BKH k-rows][BN n-cols]
            const __half* bg = Bb + (size_t)t * BKH * b_rs;
            #pragma unroll
            for (int i = 0; i < 4; i++) {
                int idx = tid + i * 256;        // 1024 chunks: r=idx>>4, g=idx&15
                int r = idx >> 4, g = idx & 15;
                cp16(bd + (uint32_t)(r * (LDBT * 2) + g * 16), bg + (size_t)r * b_rs + g * 8);
            }
        } else {
            const __half* bg = Bb + (size_t)t * BKH;
            #pragma unroll
            for (int i = 0; i < 4; i++) {
                int idx = tid + i * 256;
                int r = idx >> 3, g = idx & 7;
                cp16(bd + (uint32_t)(r * (LDAH * 2) + g * 16), bg + (size_t)r * b_rs + g * 8);
            }
        }
        asm volatile("cp.async.commit_group;" ::: "memory");
    };

    const int T = Kdim / BKH;
    fill(0);
    if (T > 1) fill(1);

    for (int t = 0; t < T; t++) {
        if (t < T - 1) asm volatile("cp.async.wait_group 1;" ::: "memory");
        else           asm volatile("cp.async.wait_group 0;" ::: "memory");
        __syncthreads();

        if (t + 2 < T) fill(t + 2);

        const int s = t % STAGES;
        const uint32_t as_s = as_base + s * A_STG_B;
        const uint32_t bs_s = bs_base + s * BSTG;

        #pragma unroll
        for (int sl = 0; sl < 4; sl++) {        // k16 slices within BK=64
            const int kh = sl * 16;
            uint32_t af[4][4], bf[4][2];
            #pragma unroll
            for (int i = 0; i < 4; i++) {
                uint32_t addr = as_s + 2u * (uint32_t)(
                    (wm + i * 16 + (mi & 1) * 8 + lr) * LDAH + kh + (mi >> 1) * 8);
                ldmx4(af[i], addr);
            }
            #pragma unroll
            for (int j2 = 0; j2 < 2; j2++) {
                uint32_t r[4];
                if (BT) {
                    // rows = k, cols = n; trans load
                    uint32_t addr = bs_s + 2u * (uint32_t)(
                        (kh + lr + (mi & 1) * 8) * LDBT + wn + j2 * 16 + (mi >> 1) * 8);
                    ldmx4t(r, addr);
                } else {
                    uint32_t addr = bs_s + 2u * (uint32_t)(
                        (wn + j2 * 16 + (mi >> 1) * 8 + lr) * LDAH + kh + (mi & 1) * 8);
                    ldmx4(r, addr);
                }
                bf[j2 * 2][0] = r[0]; bf[j2 * 2][1] = r[1];
                bf[j2 * 2 + 1][0] = r[2]; bf[j2 * 2 + 1][1] = r[3];
            }
            #pragma unroll
            for (int i = 0; i < 4; i++)
                #pragma unroll
                for (int j = 0; j < 4; j++)
                    mma_f16(acc[i][j], af[i], bf[j]);
        }
    }

    // ---- epilogue ----
    #pragma unroll
    for (int i = 0; i < 4; i++) {
        const int m0 = by * BM + wm + i * 16 + gid;
        const float bv0 = bias_m ? bias_m[m0] : 0.f;
        const float bv1 = bias_m ? bias_m[m0 + 8] : 0.f;
        #pragma unroll
        for (int j = 0; j < 4; j++) {
            const int n0 = bx * BN + wn + j * 8 + tig * 2;
            const float bn0 = bias_n ? bias_n[n0] : 0.f;
            const float bn1 = bias_n ? bias_n[n0 + 1] : 0.f;
            size_t o0 = (size_t)bz * c_zs + (size_t)m0 * c_ms + n0;
            size_t o1 = o0 + 8 * c_ms;
            float v0 = acc[i][j][0] * alpha + bv0 + bn0;
            float v1 = acc[i][j][1] * alpha + bv0 + bn1;
            float v2 = acc[i][j][2] * alpha + bv1 + bn0;
            float v3 = acc[i][j][3] * alpha + bv1 + bn1;
            if (resid) {
                v0 += resid[o0]; v1 += resid[o0 + 1];
                v2 += resid[o1]; v3 += resid[o1 + 1];
            }
            if (Ch) {
                *(__half2*)(Ch + o0) = __floats2half2_rn(v0, v1);
                *(__half2*)(Ch + o1) = __floats2half2_rn(v2, v3);
            } else {
                *(float2*)(Cf + o0) = make_float2(v0, v1);
                *(float2*)(Cf + o1) = make_float2(v2, v3);
            }
        }
    }
}

// ---------------------------------------------------------------------------
// Launch
// ---------------------------------------------------------------------------
extern "C" void kernel_launch(void* const* d_in, const int* in_sizes, int n_in,
                              void* d_out, int out_size) {
    const float* x      = (const float*)d_in[0];
    const float* gamma  = (const float*)d_in[1];
    const float* beta   = (const float*)d_in[2];
    const float* w_qkv  = (const float*)d_in[3];
    const float* b_qkv  = (const float*)d_in[4];
    const float* w_proj = (const float*)d_in[5];
    const float* b_proj = (const float*)d_in[6];
    float* out = (float*)d_out;

    float *stats;
    __half *hT, *wqkvH, *wprojH, *qkvT, *attnH, *obT;
    cudaGetSymbolAddress((void**)&stats,  g_stats);
    cudaGetSymbolAddress((void**)&hT,     g_hT);
    cudaGetSymbolAddress((void**)&wqkvH,  g_wqkvH);
    cudaGetSymbolAddress((void**)&wprojH, g_wprojH);
    cudaGetSymbolAddress((void**)&qkvT,   g_qkvT);
    cudaGetSymbolAddress((void**)&attnH,  g_attnH);
    cudaGetSymbolAddress((void**)&obT,    g_obT);

    cudaFuncSetAttribute(hgemm<0>, cudaFuncAttributeMaxDynamicSharedMemorySize, SMEM_N);
    cudaFuncSetAttribute(hgemm<1>, cudaFuncAttributeMaxDynamicSharedMemorySize, SMEM_T);

    const float scale = 1.0f / sqrtf((float)CDIM);

    // 0) convert weights to half ([o][c] is already the NT B operand)
    convert_h_kernel<<<(3 * CDIM * CDIM) / 256, 256>>>(w_qkv, wqkvH, 3 * CDIM * CDIM);
    convert_h_kernel<<<(CDIM * CDIM) / 256, 256>>>(w_proj, wprojH, CDIM * CDIM);

    // 1) GroupNorm stats, then fused normalize+transpose -> hT[t][c] half
    gn_stats_kernel<<<BATCH * 8, 256>>>(x, stats);
    gn_apply_T<<<dim3(CDIM / 32, NPIX / 32, BATCH), 256>>>(x, stats, gamma, beta, hT);

    // 2) QKV: qkvT[t][o] = sum_c hT[t][c] * wqkvH[o][c] + b_qkv[o]
    hgemm<0><<<dim3(1536 / BN, MCOLS / BM, 1), 256, SMEM_N>>>(
        hT, wqkvH, nullptr, qkvT, nullptr, b_qkv, nullptr,
        CDIM, /*a_rs*/ CDIM, 0, /*b_rs*/ CDIM, 0,
        /*c_ms*/ 1536, 0, 1.0f);

    // 3) Scores (half out): attnH[b][i][j] = scale * sum_c q[i][c] * k[j][c]
    hgemm<0><<<dim3(NPIX / BN, NPIX / BM, BATCH), 256, SMEM_N>>>(
        qkvT, qkvT + 512, nullptr, attnH, nullptr, nullptr, nullptr,
        CDIM, /*a_rs*/ 1536, /*a_zs*/ (long)NPIX * 1536,
        /*b_rs*/ 1536, /*b_zs*/ (long)NPIX * 1536,
        /*c_ms*/ NPIX, (long)NPIX * NPIX, scale);

    // 4) Softmax in place (half)
    softmax_kernel<<<BATCH * NPIX, 256>>>(attnH);

    // 5) PV (trans-B): obT[b*1024+i][c] = sum_j attnH[b][i][j] * v[b*1024+j][c]
    hgemm<1><<<dim3(CDIM / BN, NPIX / BM, BATCH), 256, SMEM_T>>>(
        attnH, qkvT + 1024, nullptr, obT, nullptr, nullptr, nullptr,
        NPIX, /*a_rs*/ NPIX, /*a_zs*/ (long)NPIX * NPIX,
        /*b_rs*/ 1536, /*b_zs*/ (long)NPIX * 1536,
        /*c_ms*/ CDIM, (long)NPIX * CDIM, 1.0f);

    // 6) Proj: out[b][o][n] = sum_c wprojH[o][c] * obT[b*1024+n][c] + b_proj[o] + x
    hgemm<0><<<dim3(NPIX / BN, CDIM / BM, BATCH), 256, SMEM_N>>>(
        wprojH, obT, out, nullptr, b_proj, nullptr, x,
        CDIM, /*a_rs*/ CDIM, 0, /*b_rs*/ CDIM, /*b_zs*/ (long)NPIX * CDIM,
        /*c_ms*/ NPIX, (long)CDIM * NPIX, 1.0f);
}

// round 12
// speedup vs baseline: 3.6173x; 1.0366x over previous
#include <cuda_runtime.h>
#include <cuda_fp16.h>
#include <math.h>
#include <stdint.h>

#define CDIM 512
#define BATCH 16
#define NPIX 1024
#define MCOLS (BATCH * NPIX)   // 16384

// ---------------------------------------------------------------------------
// Scratch (device globals)
// ---------------------------------------------------------------------------
__device__ float  g_stats [BATCH * 8 * 2];                 // mean, rstd per (b,g)
__device__ __half g_hT    [(size_t)MCOLS * CDIM];          // [t][c]
__device__ __half g_wqkvH [(size_t)3 * CDIM * CDIM];       // [o][c]
__device__ __half g_wprojH[(size_t)CDIM * CDIM];           // [o][c]
__device__ __half g_qkvT  [(size_t)MCOLS * 3 * CDIM];      // [t][o]  q|k|v
__device__ __half g_attnH [(size_t)BATCH * NPIX * NPIX];   // [b][i][j] scores -> probs
__device__ __half g_obT   [(size_t)MCOLS * CDIM];          // [t][c]

// ---------------------------------------------------------------------------
// Helpers
// ---------------------------------------------------------------------------
__device__ __forceinline__ uint32_t sm_u32(const void* p) {
    uint32_t a;
    asm("{ .reg .u64 t; cvta.to.shared.u64 t, %1; cvt.u32.u64 %0, t; }" : "=r"(a) : "l"(p));
    return a;
}
__device__ __forceinline__ void cp16(uint32_t dst, const void* src) {
    asm volatile("cp.async.cg.shared.global [%0], [%1], 16;" :: "r"(dst), "l"(src));
}
__device__ __forceinline__ void mma_f16(float c[4], const uint32_t a[4],
                                        const uint32_t b[2]) {
    asm volatile(
        "mma.sync.aligned.m16n8k16.row.col.f32.f16.f16.f32 "
        "{%0,%1,%2,%3}, {%4,%5,%6,%7}, {%8,%9}, {%0,%1,%2,%3};\n"
        : "+f"(c[0]), "+f"(c[1]), "+f"(c[2]), "+f"(c[3])
        : "r"(a[0]), "r"(a[1]), "r"(a[2]), "r"(a[3]), "r"(b[0]), "r"(b[1]));
}
__device__ __forceinline__ void ldmx4(uint32_t r[4], uint32_t addr) {
    asm volatile("ldmatrix.sync.aligned.m8n8.x4.shared.b16 {%0,%1,%2,%3}, [%4];"
                 : "=r"(r[0]), "=r"(r[1]), "=r"(r[2]), "=r"(r[3]) : "r"(addr));
}
__device__ __forceinline__ void ldmx4t(uint32_t r[4], uint32_t addr) {
    asm volatile("ldmatrix.sync.aligned.m8n8.x4.trans.shared.b16 {%0,%1,%2,%3}, [%4];"
                 : "=r"(r[0]), "=r"(r[1]), "=r"(r[2]), "=r"(r[3]) : "r"(addr));
}

// ---------------------------------------------------------------------------
// Small kernels
// ---------------------------------------------------------------------------
// convert both weight matrices in one launch: [0, 3C*C) -> wqkv, [3C*C, 4C*C) -> wproj
__global__ void convert_w_kernel(const float* __restrict__ wq, const float* __restrict__ wp,
                                 __half* __restrict__ oq, __half* __restrict__ op) {
    int i = blockIdx.x * 256 + threadIdx.x;
    const int NQ = 3 * CDIM * CDIM;
    if (i < NQ) oq[i] = __float2half(wq[i]);
    else        op[i - NQ] = __float2half(wp[i - NQ]);
}

// GroupNorm stats: one block per (b, g); writes mean, rstd
__global__ void gn_stats_kernel(const float* __restrict__ x, float* __restrict__ stats) {
    const int b = blockIdx.x >> 3;
    const int g = blockIdx.x & 7;
    const float4* xb = (const float4*)(x + ((size_t)b * CDIM + (size_t)g * 64) * NPIX);
    const int tid = threadIdx.x;
    const int NG4 = 64 * NPIX / 4;   // 16384 float4

    float s = 0.f, ss = 0.f;
    for (int i = tid; i < NG4; i += 256) {
        float4 v = xb[i];
        s  += v.x + v.y + v.z + v.w;
        ss += v.x * v.x + v.y * v.y + v.z * v.z + v.w * v.w;
    }
    #pragma unroll
    for (int o = 16; o > 0; o >>= 1) {
        s  += __shfl_xor_sync(0xffffffffu, s, o);
        ss += __shfl_xor_sync(0xffffffffu, ss, o);
    }
    __shared__ float sh_s[8], sh_ss[8];
    if ((tid & 31) == 0) { sh_s[tid >> 5] = s; sh_ss[tid >> 5] = ss; }
    __syncthreads();
    if (tid == 0) {
        float s2 = 0.f, ss2 = 0.f;
        #pragma unroll
        for (int i = 0; i < 8; i++) { s2 += sh_s[i]; ss2 += sh_ss[i]; }
        const float mean = s2 * (1.f / 65536.f);
        const float var  = ss2 * (1.f / 65536.f) - mean * mean;
        stats[blockIdx.x * 2 + 0] = mean;
        stats[blockIdx.x * 2 + 1] = rsqrtf(var + 1e-5f);
    }
}

// Fused normalize + transpose: x[b][c][n] -> hT[b*1024+n][c] (half)
__global__ void gn_apply_T(const float* __restrict__ x, const float* __restrict__ stats,
                           const float* __restrict__ gamma, const float* __restrict__ beta,
                           __half* __restrict__ hT) {
    __shared__ float t[32][33];
    const int b = blockIdx.z;
    const int tx = threadIdx.x & 31, ty = threadIdx.x >> 5;
    const int c0 = blockIdx.x * 32, n0 = blockIdx.y * 32;
    const float* xb = x + (size_t)b * CDIM * NPIX;
    #pragma unroll
    for (int k = 0; k < 4; k++) {
        const int c = c0 + ty + 8 * k;
        const float mean = stats[(b * 8 + (c >> 6)) * 2 + 0];
        const float rstd = stats[(b * 8 + (c >> 6)) * 2 + 1];
        float v = xb[(size_t)c * NPIX + n0 + tx];
        t[ty + 8 * k][tx] = (v - mean) * rstd * gamma[c] + beta[c];
    }
    __syncthreads();
    #pragma unroll
    for (int k = 0; k < 4; k++) {
        const int n = n0 + ty + 8 * k;
        hT[(size_t)(b * NPIX + n) * CDIM + c0 + tx] = __float2half(t[tx][ty + 8 * k]);
    }
}

// in-place softmax over half rows of length NPIX; one WARP per row, no barriers.
// grid: (BATCH*NPIX/4) blocks of 128 threads (4 warps).
__global__ void softmax_kernel(__half* __restrict__ attnH) {
    const int warp = threadIdx.x >> 5, lane = threadIdx.x & 31;
    __half2* row = (__half2*)(attnH + ((size_t)blockIdx.x * 4 + warp) * NPIX);

    float2 v[16];
    float mx = -1e30f;
    #pragma unroll
    for (int i = 0; i < 16; i++) {
        v[i] = __half22float2(row[lane + i * 32]);
        mx = fmaxf(mx, fmaxf(v[i].x, v[i].y));
    }
    #pragma unroll
    for (int o = 16; o > 0; o >>= 1)
        mx = fmaxf(mx, __shfl_xor_sync(0xffffffffu, mx, o));

    float s = 0.f;
    #pragma unroll
    for (int i = 0; i < 16; i++) {
        v[i].x = __expf(v[i].x - mx);
        v[i].y = __expf(v[i].y - mx);
        s += v[i].x + v[i].y;
    }
    #pragma unroll
    for (int o = 16; o > 0; o >>= 1)
        s += __shfl_xor_sync(0xffffffffu, s, o);

    const float inv = 1.f / s;
    #pragma unroll
    for (int i = 0; i < 16; i++)
        row[lane + i * 32] = __floats2half2_rn(v[i].x * inv, v[i].y * inv);
}

// ---------------------------------------------------------------------------
// FP16 GEMM (fp32 accumulate), ldmatrix fragment loads.
//   D[bz, m, n] = alpha * sum_k A[m][k] * B_k_n (+bias_m[m]) (+bias_n[n]) (+resid)
// A: [M rows][K] k-contiguous half, row stride a_rs.
// BT=0: B is [N rows][K] k-contiguous (NT).  BT=1: B is [K rows][N] n-contiguous
//       (row stride b_rs), loaded via ldmatrix.trans.
// Tile 128x128x64, 256 threads, 8 warps (2m x 4n), warp tile 64x32.
// 3-stage cp.async, 2 CTAs/SM.
// ---------------------------------------------------------------------------
#define BM 128
#define BN 128
#define BKH 64
#define STAGES 3
#define LDAH 72                     // halves per A smem row (64 + 8 pad)
#define LDBT 136                    // halves per trans-B smem row (128 + 8 pad)
#define A_STG_B (BM * LDAH * 2)     // 18432 bytes
#define B_STG_N (BN * LDAH * 2)     // 18432 bytes (BT=0)
#define B_STG_T (BKH * LDBT * 2)    // 17408 bytes (BT=1)
#define SMEM_N (STAGES * (A_STG_B + B_STG_N))   // 110592
#define SMEM_T (STAGES * (A_STG_B + B_STG_T))   // 107520

template <int BT>
__global__ __launch_bounds__(256, 2)
void hgemm(const __half* __restrict__ A, const __half* __restrict__ B,
           float* __restrict__ Cf, __half* __restrict__ Ch,
           const float* __restrict__ bias_m, const float* __restrict__ bias_n,
           const float* __restrict__ resid,
           int Kdim, long a_rs, long a_zs, long b_rs, long b_zs,
           long c_ms, long c_zs, float alpha) {
    extern __shared__ char smem_raw[];
    const uint32_t as_base = sm_u32(smem_raw);
    const uint32_t bs_base = as_base + STAGES * A_STG_B;
    const int BSTG = BT ? B_STG_T : B_STG_N;

    const int tid = threadIdx.x, warp = tid >> 5, lane = tid & 31;
    const int gid = lane >> 2, tig = lane & 3;
    const int bx = blockIdx.x, by = blockIdx.y, bz = blockIdx.z;
    const int wm = (warp & 1) * 64;
    const int wn = (warp >> 1) * 32;
    const int lr = lane & 7, mi = lane >> 3;

    const __half* Ab = A + (size_t)bz * a_zs + (size_t)by * BM * a_rs;
    const __half* Bb = BT ? (B + (size_t)bz * b_zs + (size_t)bx * BN)
                          : (B + (size_t)bz * b_zs + (size_t)bx * BN * b_rs);

    float acc[4][4][4];
    #pragma unroll
    for (int i = 0; i < 4; i++)
        #pragma unroll
        for (int j = 0; j < 4; j++)
            #pragma unroll
            for (int r = 0; r < 4; r++) acc[i][j][r] = 0.f;

    auto fill = [&](int t) {
        const int s = t % STAGES;
        const __half* ag = Ab + (size_t)t * BKH;
        const uint32_t ad = as_base + s * A_STG_B;
        #pragma unroll
        for (int i = 0; i < 4; i++) {
            int idx = tid + i * 256;
            int r = idx >> 3, g = idx & 7;
            cp16(ad + (uint32_t)(r * (LDAH * 2) + g * 16), ag + (size_t)r * a_rs + g * 8);
        }
        const uint32_t bd = bs_base + s * BSTG;
        if (BT) {
            const __half* bg = Bb + (size_t)t * BKH * b_rs;
            #pragma unroll
            for (int i = 0; i < 4; i++) {
                int idx = tid + i * 256;
                int r = idx >> 4, g = idx & 15;
                cp16(bd + (uint32_t)(r * (LDBT * 2) + g * 16), bg + (size_t)r * b_rs + g * 8);
            }
        } else {
            const __half* bg = Bb + (size_t)t * BKH;
            #pragma unroll
            for (int i = 0; i < 4; i++) {
                int idx = tid + i * 256;
                int r = idx >> 3, g = idx & 7;
                cp16(bd + (uint32_t)(r * (LDAH * 2) + g * 16), bg + (size_t)r * b_rs + g * 8);
            }
        }
        asm volatile("cp.async.commit_group;" ::: "memory");
    };

    const int T = Kdim / BKH;
    fill(0);
    if (T > 1) fill(1);

    for (int t = 0; t < T; t++) {
        if (t < T - 1) asm volatile("cp.async.wait_group 1;" ::: "memory");
        else           asm volatile("cp.async.wait_group 0;" ::: "memory");
        __syncthreads();

        if (t + 2 < T) fill(t + 2);

        const int s = t % STAGES;
        const uint32_t as_s = as_base + s * A_STG_B;
        const uint32_t bs_s = bs_base + s * BSTG;

        #pragma unroll
        for (int sl = 0; sl < 4; sl++) {        // k16 slices within BK=64
            const int kh = sl * 16;
            uint32_t af[4][4], bf[4][2];
            #pragma unroll
            for (int i = 0; i < 4; i++) {
                uint32_t addr = as_s + 2u * (uint32_t)(
                    (wm + i * 16 + (mi & 1) * 8 + lr) * LDAH + kh + (mi >> 1) * 8);
                ldmx4(af[i], addr);
            }
            #pragma unroll
            for (int j2 = 0; j2 < 2; j2++) {
                uint32_t r[4];
                if (BT) {
                    uint32_t addr = bs_s + 2u * (uint32_t)(
                        (kh + lr + (mi & 1) * 8) * LDBT + wn + j2 * 16 + (mi >> 1) * 8);
                    ldmx4t(r, addr);
                } else {
                    uint32_t addr = bs_s + 2u * (uint32_t)(
                        (wn + j2 * 16 + (mi >> 1) * 8 + lr) * LDAH + kh + (mi & 1) * 8);
                    ldmx4(r, addr);
                }
                bf[j2 * 2][0] = r[0]; bf[j2 * 2][1] = r[1];
                bf[j2 * 2 + 1][0] = r[2]; bf[j2 * 2 + 1][1] = r[3];
            }
            #pragma unroll
            for (int i = 0; i < 4; i++)
                #pragma unroll
                for (int j = 0; j < 4; j++)
                    mma_f16(acc[i][j], af[i], bf[j]);
        }
    }

    // ---- epilogue ----
    #pragma unroll
    for (int i = 0; i < 4; i++) {
        const int m0 = by * BM + wm + i * 16 + gid;
        const float bv0 = bias_m ? bias_m[m0] : 0.f;
        const float bv1 = bias_m ? bias_m[m0 + 8] : 0.f;
        #pragma unroll
        for (int j = 0; j < 4; j++) {
            const int n0 = bx * BN + wn + j * 8 + tig * 2;
            const float bn0 = bias_n ? bias_n[n0] : 0.f;
            const float bn1 = bias_n ? bias_n[n0 + 1] : 0.f;
            size_t o0 = (size_t)bz * c_zs + (size_t)m0 * c_ms + n0;
            size_t o1 = o0 + 8 * c_ms;
            float v0 = acc[i][j][0] * alpha + bv0 + bn0;
            float v1 = acc[i][j][1] * alpha + bv0 + bn1;
            float v2 = acc[i][j][2] * alpha + bv1 + bn0;
            float v3 = acc[i][j][3] * alpha + bv1 + bn1;
            if (resid) {
                v0 += resid[o0]; v1 += resid[o0 + 1];
                v2 += resid[o1]; v3 += resid[o1 + 1];
            }
            if (Ch) {
                *(__half2*)(Ch + o0) = __floats2half2_rn(v0, v1);
                *(__half2*)(Ch + o1) = __floats2half2_rn(v2, v3);
            } else {
                *(float2*)(Cf + o0) = make_float2(v0, v1);
                *(float2*)(Cf + o1) = make_float2(v2, v3);
            }
        }
    }
}

// ---------------------------------------------------------------------------
// Launch
// ---------------------------------------------------------------------------
extern "C" void kernel_launch(void* const* d_in, const int* in_sizes, int n_in,
                              void* d_out, int out_size) {
    const float* x      = (const float*)d_in[0];
    const float* gamma  = (const float*)d_in[1];
    const float* beta   = (const float*)d_in[2];
    const float* w_qkv  = (const float*)d_in[3];
    const float* b_qkv  = (const float*)d_in[4];
    const float* w_proj = (const float*)d_in[5];
    const float* b_proj = (const float*)d_in[6];
    float* out = (float*)d_out;

    float *stats;
    __half *hT, *wqkvH, *wprojH, *qkvT, *attnH, *obT;
    cudaGetSymbolAddress((void**)&stats,  g_stats);
    cudaGetSymbolAddress((void**)&hT,     g_hT);
    cudaGetSymbolAddress((void**)&wqkvH,  g_wqkvH);
    cudaGetSymbolAddress((void**)&wprojH, g_wprojH);
    cudaGetSymbolAddress((void**)&qkvT,   g_qkvT);
    cudaGetSymbolAddress((void**)&attnH,  g_attnH);
    cudaGetSymbolAddress((void**)&obT,    g_obT);

    cudaFuncSetAttribute(hgemm<0>, cudaFuncAttributeMaxDynamicSharedMemorySize, SMEM_N);
    cudaFuncSetAttribute(hgemm<1>, cudaFuncAttributeMaxDynamicSharedMemorySize, SMEM_T);

    const float scale = 1.0f / sqrtf((float)CDIM);

    // 0) convert both weight matrices to half (one launch)
    convert_w_kernel<<<(4 * CDIM * CDIM) / 256, 256>>>(w_qkv, w_proj, wqkvH, wprojH);

    // 1) GroupNorm stats, then fused normalize+transpose -> hT[t][c] half
    gn_stats_kernel<<<BATCH * 8, 256>>>(x, stats);
    gn_apply_T<<<dim3(CDIM / 32, NPIX / 32, BATCH), 256>>>(x, stats, gamma, beta, hT);

    // 2) QKV: qkvT[t][o] = sum_c hT[t][c] * wqkvH[o][c] + b_qkv[o]
    hgemm<0><<<dim3(1536 / BN, MCOLS / BM, 1), 256, SMEM_N>>>(
        hT, wqkvH, nullptr, qkvT, nullptr, b_qkv, nullptr,
        CDIM, /*a_rs*/ CDIM, 0, /*b_rs*/ CDIM, 0,
        /*c_ms*/ 1536, 0, 1.0f);

    // 3) Scores (half out): attnH[b][i][j] = scale * sum_c q[i][c] * k[j][c]
    hgemm<0><<<dim3(NPIX / BN, NPIX / BM, BATCH), 256, SMEM_N>>>(
        qkvT, qkvT + 512, nullptr, attnH, nullptr, nullptr, nullptr,
        CDIM, /*a_rs*/ 1536, /*a_zs*/ (long)NPIX * 1536,
        /*b_rs*/ 1536, /*b_zs*/ (long)NPIX * 1536,
        /*c_ms*/ NPIX, (long)NPIX * NPIX, scale);

    // 4) Softmax in place (half), warp-per-row
    softmax_kernel<<<BATCH * NPIX / 4, 128>>>(attnH);

    // 5) PV (trans-B): obT[b*1024+i][c] = sum_j attnH[b][i][j] * v[b*1024+j][c]
    hgemm<1><<<dim3(CDIM / BN, NPIX / BM, BATCH), 256, SMEM_T>>>(
        attnH, qkvT + 1024, nullptr, obT, nullptr, nullptr, nullptr,
        NPIX, /*a_rs*/ NPIX, /*a_zs*/ (long)NPIX * NPIX,
        /*b_rs*/ 1536, /*b_zs*/ (long)NPIX * 1536,
        /*c_ms*/ CDIM, (long)NPIX * CDIM, 1.0f);

    // 6) Proj: out[b][o][n] = sum_c wprojH[o][c] * obT[b*1024+n][c] + b_proj[o] + x
    hgemm<0><<<dim3(NPIX / BN, CDIM / BM, BATCH), 256, SMEM_N>>>(
        wprojH, obT, out, nullptr, b_proj, nullptr, x,
        CDIM, /*a_rs*/ CDIM, 0, /*b_rs*/ CDIM, /*b_zs*/ (long)NPIX * CDIM,
        /*c_ms*/ NPIX, (long)CDIM * NPIX, 1.0f);
}

// round 14
// speedup vs baseline: 3.6418x; 1.0068x over previous
#include <cuda_runtime.h>
#include <cuda_fp16.h>
#include <math.h>
#include <stdint.h>

#define CDIM 512
#define BATCH 16
#define NPIX 1024
#define MCOLS (BATCH * NPIX)   // 16384

// ---------------------------------------------------------------------------
// Scratch (device globals)
// ---------------------------------------------------------------------------
__device__ float  g_stats [BATCH * 8 * 2];                 // mean, rstd per (b,g)
__device__ __half g_hT    [(size_t)MCOLS * CDIM];          // [t][c]
__device__ __half g_wqkvH [(size_t)3 * CDIM * CDIM];       // [o][c]
__device__ __half g_wprojH[(size_t)CDIM * CDIM];           // [o][c]
__device__ __half g_qkvT  [(size_t)MCOLS * 3 * CDIM];      // [t][o]  q|k|v
__device__ __half g_attnH [(size_t)BATCH * NPIX * NPIX];   // [b][i][j] scores -> probs
__device__ __half g_obT   [(size_t)MCOLS * CDIM];          // [t][c]

// ---------------------------------------------------------------------------
// Helpers
// ---------------------------------------------------------------------------
__device__ __forceinline__ uint32_t sm_u32(const void* p) {
    uint32_t a;
    asm("{ .reg .u64 t; cvta.to.shared.u64 t, %1; cvt.u32.u64 %0, t; }" : "=r"(a) : "l"(p));
    return a;
}
__device__ __forceinline__ void cp16(uint32_t dst, const void* src) {
    asm volatile("cp.async.cg.shared.global [%0], [%1], 16;" :: "r"(dst), "l"(src));
}
__device__ __forceinline__ void mma_f16(float c[4], const uint32_t a[4],
                                        const uint32_t b[2]) {
    asm volatile(
        "mma.sync.aligned.m16n8k16.row.col.f32.f16.f16.f32 "
        "{%0,%1,%2,%3}, {%4,%5,%6,%7}, {%8,%9}, {%0,%1,%2,%3};\n"
        : "+f"(c[0]), "+f"(c[1]), "+f"(c[2]), "+f"(c[3])
        : "r"(a[0]), "r"(a[1]), "r"(a[2]), "r"(a[3]), "r"(b[0]), "r"(b[1]));
}
__device__ __forceinline__ void ldmx4(uint32_t r[4], uint32_t addr) {
    asm volatile("ldmatrix.sync.aligned.m8n8.x4.shared.b16 {%0,%1,%2,%3}, [%4];"
                 : "=r"(r[0]), "=r"(r[1]), "=r"(r[2]), "=r"(r[3]) : "r"(addr));
}
__device__ __forceinline__ void ldmx4t(uint32_t r[4], uint32_t addr) {
    asm volatile("ldmatrix.sync.aligned.m8n8.x4.trans.shared.b16 {%0,%1,%2,%3}, [%4];"
                 : "=r"(r[0]), "=r"(r[1]), "=r"(r[2]), "=r"(r[3]) : "r"(addr));
}

// ---------------------------------------------------------------------------
// Small kernels
// ---------------------------------------------------------------------------
// convert both weight matrices in one launch
__global__ void convert_w_kernel(const float* __restrict__ wq, const float* __restrict__ wp,
                                 __half* __restrict__ oq, __half* __restrict__ op) {
    int i = blockIdx.x * 256 + threadIdx.x;
    const int NQ = 3 * CDIM * CDIM;
    if (i < NQ) oq[i] = __float2half(wq[i]);
    else        op[i - NQ] = __float2half(wp[i - NQ]);
}

// GroupNorm stats: one block per (b, g); writes mean, rstd
__global__ void gn_stats_kernel(const float* __restrict__ x, float* __restrict__ stats) {
    const int b = blockIdx.x >> 3;
    const int g = blockIdx.x & 7;
    const float4* xb = (const float4*)(x + ((size_t)b * CDIM + (size_t)g * 64) * NPIX);
    const int tid = threadIdx.x;
    const int NG4 = 64 * NPIX / 4;   // 16384 float4

    float s = 0.f, ss = 0.f;
    for (int i = tid; i < NG4; i += 256) {
        float4 v = xb[i];
        s  += v.x + v.y + v.z + v.w;
        ss += v.x * v.x + v.y * v.y + v.z * v.z + v.w * v.w;
    }
    #pragma unroll
    for (int o = 16; o > 0; o >>= 1) {
        s  += __shfl_xor_sync(0xffffffffu, s, o);
        ss += __shfl_xor_sync(0xffffffffu, ss, o);
    }
    __shared__ float sh_s[8], sh_ss[8];
    if ((tid & 31) == 0) { sh_s[tid >> 5] = s; sh_ss[tid >> 5] = ss; }
    __syncthreads();
    if (tid == 0) {
        float s2 = 0.f, ss2 = 0.f;
        #pragma unroll
        for (int i = 0; i < 8; i++) { s2 += sh_s[i]; ss2 += sh_ss[i]; }
        const float mean = s2 * (1.f / 65536.f);
        const float var  = ss2 * (1.f / 65536.f) - mean * mean;
        stats[blockIdx.x * 2 + 0] = mean;
        stats[blockIdx.x * 2 + 1] = rsqrtf(var + 1e-5f);
    }
}

// Fused normalize + transpose: x[b][c][n] -> hT[b*1024+n][c] (half)
// 64(c) x 64(n) tile per 256-thread block; 256B coalesced reads, 128B half2 writes.
// grid: (CDIM/64, NPIX/64, BATCH)
__global__ void gn_apply_T(const float* __restrict__ x, const float* __restrict__ stats,
                           const float* __restrict__ gamma, const float* __restrict__ beta,
                           __half* __restrict__ hT) {
    __shared__ float sm[64][65];
    __shared__ float sc[64], sf[64];
    const int b = blockIdx.z;
    const int c0 = blockIdx.x * 64, n0 = blockIdx.y * 64;
    const int tid = threadIdx.x;

    if (tid < 64) {
        const int c = c0 + tid;
        const float mean = stats[(b * 8 + (c >> 6)) * 2 + 0];
        const float rstd = stats[(b * 8 + (c >> 6)) * 2 + 1];
        const float g = gamma[c];
        sc[tid] = rstd * g;
        sf[tid] = beta[c] - mean * rstd * g;
    }
    __syncthreads();

    const float* xb = x + (size_t)b * CDIM * NPIX;
    #pragma unroll
    for (int p = 0; p < 16; p++) {
        const int idx = tid + p * 256;
        const int r = idx >> 6, col = idx & 63;
        sm[r][col] = xb[(size_t)(c0 + r) * NPIX + n0 + col] * sc[r] + sf[r];
    }
    __syncthreads();

    // write hT[t][c]: t = n0+tn (64 rows), c = c0 + 2l (+1); 128B per row
    const int l = tid & 31;
    #pragma unroll
    for (int p = 0; p < 8; p++) {
        const int tn = (tid >> 5) + p * 8;
        __half2 v = __floats2half2_rn(sm[2 * l][tn], sm[2 * l + 1][tn]);
        *(__half2*)(hT + (size_t)(b * NPIX + n0 + tn) * CDIM + c0 + 2 * l) = v;
    }
}

// in-place softmax over half rows of length NPIX; one WARP per row, no barriers.
// grid: (BATCH*NPIX/4) blocks of 128 threads (4 warps).
__global__ void softmax_kernel(__half* __restrict__ attnH) {
    const int warp = threadIdx.x >> 5, lane = threadIdx.x & 31;
    __half2* row = (__half2*)(attnH + ((size_t)blockIdx.x * 4 + warp) * NPIX);

    float2 v[16];
    float mx = -1e30f;
    #pragma unroll
    for (int i = 0; i < 16; i++) {
        v[i] = __half22float2(row[lane + i * 32]);
        mx = fmaxf(mx, fmaxf(v[i].x, v[i].y));
    }
    #pragma unroll
    for (int o = 16; o > 0; o >>= 1)
        mx = fmaxf(mx, __shfl_xor_sync(0xffffffffu, mx, o));

    float s = 0.f;
    #pragma unroll
    for (int i = 0; i < 16; i++) {
        v[i].x = __expf(v[i].x - mx);
        v[i].y = __expf(v[i].y - mx);
        s += v[i].x + v[i].y;
    }
    #pragma unroll
    for (int o = 16; o > 0; o >>= 1)
        s += __shfl_xor_sync(0xffffffffu, s, o);

    const float inv = 1.f / s;
    #pragma unroll
    for (int i = 0; i < 16; i++)
        row[lane + i * 32] = __floats2half2_rn(v[i].x * inv, v[i].y * inv);
}

// ---------------------------------------------------------------------------
// FP16 GEMM (fp32 accumulate), ldmatrix fragment loads.
//   D[bz, m, n] = alpha * sum_k A[m][k] * B_k_n (+bias_m[m]) (+bias_n[n]) (+resid)
// A: [M rows][K] k-contiguous half, row stride a_rs.
// BT=0: B is [N rows][K] k-contiguous (NT).  BT=1: B is [K rows][N] n-contiguous
//       (row stride b_rs), loaded via ldmatrix.trans.
// Tile 128x128x64, 256 threads, 8 warps (2m x 4n), warp tile 64x32.
// 3-stage cp.async, 2 CTAs/SM.
// ---------------------------------------------------------------------------
#define BM 128
#define BN 128
#define BKH 64
#define STAGES 3
#define LDAH 72                     // halves per A smem row (64 + 8 pad)
#define LDBT 136                    // halves per trans-B smem row (128 + 8 pad)
#define A_STG_B (BM * LDAH * 2)     // 18432 bytes
#define B_STG_N (BN * LDAH * 2)     // 18432 bytes (BT=0)
#define B_STG_T (BKH * LDBT * 2)    // 17408 bytes (BT=1)
#define SMEM_N (STAGES * (A_STG_B + B_STG_N))   // 110592
#define SMEM_T (STAGES * (A_STG_B + B_STG_T))   // 107520

template <int BT>
__global__ __launch_bounds__(256, 2)
void hgemm(const __half* __restrict__ A, const __half* __restrict__ B,
           float* __restrict__ Cf, __half* __restrict__ Ch,
           const float* __restrict__ bias_m, const float* __restrict__ bias_n,
           const float* __restrict__ resid,
           int Kdim, long a_rs, long a_zs, long b_rs, long b_zs,
           long c_ms, long c_zs, float alpha) {
    extern __shared__ char smem_raw[];
    const uint32_t as_base = sm_u32(smem_raw);
    const uint32_t bs_base = as_base + STAGES * A_STG_B;
    const int BSTG = BT ? B_STG_T : B_STG_N;

    const int tid = threadIdx.x, warp = tid >> 5, lane = tid & 31;
    const int gid = lane >> 2, tig = lane & 3;
    const int bx = blockIdx.x, by = blockIdx.y, bz = blockIdx.z;
    const int wm = (warp & 1) * 64;
    const int wn = (warp >> 1) * 32;
    const int lr = lane & 7, mi = lane >> 3;

    const __half* Ab = A + (size_t)bz * a_zs + (size_t)by * BM * a_rs;
    const __half* Bb = BT ? (B + (size_t)bz * b_zs + (size_t)bx * BN)
                          : (B + (size_t)bz * b_zs + (size_t)bx * BN * b_rs);

    float acc[4][4][4];
    #pragma unroll
    for (int i = 0; i < 4; i++)
        #pragma unroll
        for (int j = 0; j < 4; j++)
            #pragma unroll
            for (int r = 0; r < 4; r++) acc[i][j][r] = 0.f;

    auto fill = [&](int t) {
        const int s = t % STAGES;
        const __half* ag = Ab + (size_t)t * BKH;
        const uint32_t ad = as_base + s * A_STG_B;
        #pragma unroll
        for (int i = 0; i < 4; i++) {
            int idx = tid + i * 256;
            int r = idx >> 3, g = idx & 7;
            cp16(ad + (uint32_t)(r * (LDAH * 2) + g * 16), ag + (size_t)r * a_rs + g * 8);
        }
        const uint32_t bd = bs_base + s * BSTG;
        if (BT) {
            const __half* bg = Bb + (size_t)t * BKH * b_rs;
            #pragma unroll
            for (int i = 0; i < 4; i++) {
                int idx = tid + i * 256;
                int r = idx >> 4, g = idx & 15;
                cp16(bd + (uint32_t)(r * (LDBT * 2) + g * 16), bg + (size_t)r * b_rs + g * 8);
            }
        } else {
            const __half* bg = Bb + (size_t)t * BKH;
            #pragma unroll
            for (int i = 0; i < 4; i++) {
                int idx = tid + i * 256;
                int r = idx >> 3, g = idx & 7;
                cp16(bd + (uint32_t)(r * (LDAH * 2) + g * 16), bg + (size_t)r * b_rs + g * 8);
            }
        }
        asm volatile("cp.async.commit_group;" ::: "memory");
    };

    const int T = Kdim / BKH;
    fill(0);
    if (T > 1) fill(1);

    for (int t = 0; t < T; t++) {
        if (t < T - 1) asm volatile("cp.async.wait_group 1;" ::: "memory");
        else           asm volatile("cp.async.wait_group 0;" ::: "memory");
        __syncthreads();

        if (t + 2 < T) fill(t + 2);

        const int s = t % STAGES;
        const uint32_t as_s = as_base + s * A_STG_B;
        const uint32_t bs_s = bs_base + s * BSTG;

        #pragma unroll
        for (int sl = 0; sl < 4; sl++) {        // k16 slices within BK=64
            const int kh = sl * 16;
            uint32_t af[4][4], bf[4][2];
            #pragma unroll
            for (int i = 0; i < 4; i++) {
                uint32_t addr = as_s + 2u * (uint32_t)(
                    (wm + i * 16 + (mi & 1) * 8 + lr) * LDAH + kh + (mi >> 1) * 8);
                ldmx4(af[i], addr);
            }
            #pragma unroll
            for (int j2 = 0; j2 < 2; j2++) {
                uint32_t r[4];
                if (BT) {
                    uint32_t addr = bs_s + 2u * (uint32_t)(
                        (kh + lr + (mi & 1) * 8) * LDBT + wn + j2 * 16 + (mi >> 1) * 8);
                    ldmx4t(r, addr);
                } else {
                    uint32_t addr = bs_s + 2u * (uint32_t)(
                        (wn + j2 * 16 + (mi >> 1) * 8 + lr) * LDAH + kh + (mi & 1) * 8);
                    ldmx4(r, addr);
                }
                bf[j2 * 2][0] = r[0]; bf[j2 * 2][1] = r[1];
                bf[j2 * 2 + 1][0] = r[2]; bf[j2 * 2 + 1][1] = r[3];
            }
            #pragma unroll
            for (int i = 0; i < 4; i++)
                #pragma unroll
                for (int j = 0; j < 4; j++)
                    mma_f16(acc[i][j], af[i], bf[j]);
        }
    }

    // ---- epilogue ----
    #pragma unroll
    for (int i = 0; i < 4; i++) {
        const int m0 = by * BM + wm + i * 16 + gid;
        const float bv0 = bias_m ? bias_m[m0] : 0.f;
        const float bv1 = bias_m ? bias_m[m0 + 8] : 0.f;
        #pragma unroll
        for (int j = 0; j < 4; j++) {
            const int n0 = bx * BN + wn + j * 8 + tig * 2;
            const float bn0 = bias_n ? bias_n[n0] : 0.f;
            const float bn1 = bias_n ? bias_n[n0 + 1] : 0.f;
            size_t o0 = (size_t)bz * c_zs + (size_t)m0 * c_ms + n0;
            size_t o1 = o0 + 8 * c_ms;
            float v0 = acc[i][j][0] * alpha + bv0 + bn0;
            float v1 = acc[i][j][1] * alpha + bv0 + bn1;
            float v2 = acc[i][j][2] * alpha + bv1 + bn0;
            float v3 = acc[i][j][3] * alpha + bv1 + bn1;
            if (resid) {
                v0 += resid[o0]; v1 += resid[o0 + 1];
                v2 += resid[o1]; v3 += resid[o1 + 1];
            }
            if (Ch) {
                *(__half2*)(Ch + o0) = __floats2half2_rn(v0, v1);
                *(__half2*)(Ch + o1) = __floats2half2_rn(v2, v3);
            } else {
                *(float2*)(Cf + o0) = make_float2(v0, v1);
                *(float2*)(Cf + o1) = make_float2(v2, v3);
            }
        }
    }
}

// ---------------------------------------------------------------------------
// Launch
// ---------------------------------------------------------------------------
extern "C" void kernel_launch(void* const* d_in, const int* in_sizes, int n_in,
                              void* d_out, int out_size) {
    const float* x      = (const float*)d_in[0];
    const float* gamma  = (const float*)d_in[1];
    const float* beta   = (const float*)d_in[2];
    const float* w_qkv  = (const float*)d_in[3];
    const float* b_qkv  = (const float*)d_in[4];
    const float* w_proj = (const float*)d_in[5];
    const float* b_proj = (const float*)d_in[6];
    float* out = (float*)d_out;

    float *stats;
    __half *hT, *wqkvH, *wprojH, *qkvT, *attnH, *obT;
    cudaGetSymbolAddress((void**)&stats,  g_stats);
    cudaGetSymbolAddress((void**)&hT,     g_hT);
    cudaGetSymbolAddress((void**)&wqkvH,  g_wqkvH);
    cudaGetSymbolAddress((void**)&wprojH, g_wprojH);
    cudaGetSymbolAddress((void**)&qkvT,   g_qkvT);
    cudaGetSymbolAddress((void**)&attnH,  g_attnH);
    cudaGetSymbolAddress((void**)&obT,    g_obT);

    cudaFuncSetAttribute(hgemm<0>, cudaFuncAttributeMaxDynamicSharedMemorySize, SMEM_N);
    cudaFuncSetAttribute(hgemm<1>, cudaFuncAttributeMaxDynamicSharedMemorySize, SMEM_T);

    const float scale = 1.0f / sqrtf((float)CDIM);

    // 0) convert both weight matrices to half (one launch)
    convert_w_kernel<<<(4 * CDIM * CDIM) / 256, 256>>>(w_qkv, w_proj, wqkvH, wprojH);

    // 1) GroupNorm stats, then fused normalize+transpose -> hT[t][c] half
    gn_stats_kernel<<<BATCH * 8, 256>>>(x, stats);
    gn_apply_T<<<dim3(CDIM / 64, NPIX / 64, BATCH), 256>>>(x, stats, gamma, beta, hT);

    // 2) QKV: qkvT[t][o] = sum_c hT[t][c] * wqkvH[o][c] + b_qkv[o]
    hgemm<0><<<dim3(1536 / BN, MCOLS / BM, 1), 256, SMEM_N>>>(
        hT, wqkvH, nullptr, qkvT, nullptr, b_qkv, nullptr,
        CDIM, /*a_rs*/ CDIM, 0, /*b_rs*/ CDIM, 0,
        /*c_ms*/ 1536, 0, 1.0f);

    // 3) Scores (half out): attnH[b][i][j] = scale * sum_c q[i][c] * k[j][c]
    hgemm<0><<<dim3(NPIX / BN, NPIX / BM, BATCH), 256, SMEM_N>>>(
        qkvT, qkvT + 512, nullptr, attnH, nullptr, nullptr, nullptr,
        CDIM, /*a_rs*/ 1536, /*a_zs*/ (long)NPIX * 1536,
        /*b_rs*/ 1536, /*b_zs*/ (long)NPIX * 1536,
        /*c_ms*/ NPIX, (long)NPIX * NPIX, scale);

    // 4) Softmax in place (half), warp-per-row
    softmax_kernel<<<BATCH * NPIX / 4, 128>>>(attnH);

    // 5) PV (trans-B): obT[b*1024+i][c] = sum_j attnH[b][i][j] * v[b*1024+j][c]
    hgemm<1><<<dim3(CDIM / BN, NPIX / BM, BATCH), 256, SMEM_T>>>(
        attnH, qkvT + 1024, nullptr, obT, nullptr, nullptr, nullptr,
        NPIX, /*a_rs*/ NPIX, /*a_zs*/ (long)NPIX * NPIX,
        /*b_rs*/ 1536, /*b_zs*/ (long)NPIX * 1536,
        /*c_ms*/ CDIM, (long)NPIX * CDIM, 1.0f);

    // 6) Proj: out[b][o][n] = sum_c wprojH[o][c] * obT[b*1024+n][c] + b_proj[o] + x
    hgemm<0><<<dim3(NPIX / BN, CDIM / BM, BATCH), 256, SMEM_N>>>(
        wprojH, obT, out, nullptr, b_proj, nullptr, x,
        CDIM, /*a_rs*/ CDIM, 0, /*b_rs*/ CDIM, /*b_zs*/ (long)NPIX * CDIM,
        /*c_ms*/ NPIX, (long)CDIM * NPIX, 1.0f);
}

// round 16
// speedup vs baseline: 3.7364x; 1.0260x over previous
#include <cuda_runtime.h>
#include <cuda_fp16.h>
#include <math.h>
#include <stdint.h>

#define CDIM 512
#define BATCH 16
#define NPIX 1024
#define MCOLS (BATCH * NPIX)   // 16384

// ---------------------------------------------------------------------------
// Scratch (device globals)
// ---------------------------------------------------------------------------
__device__ float  g_stats [BATCH * 8 * 2];                 // mean, rstd per (b,g)
__device__ __half g_hT    [(size_t)MCOLS * CDIM];          // [t][c]
__device__ __half g_wqkvH [(size_t)3 * CDIM * CDIM];       // [o][c]
__device__ __half g_wprojH[(size_t)CDIM * CDIM];           // [o][c]
__device__ __half g_qkvT  [(size_t)MCOLS * 3 * CDIM];      // [t][o]  q|k|v
__device__ __half g_attnH [(size_t)BATCH * NPIX * NPIX];   // [b][i][j] scores -> probs
__device__ __half g_obT   [(size_t)MCOLS * CDIM];          // [t][c]

// ---------------------------------------------------------------------------
// Helpers
// ---------------------------------------------------------------------------
__device__ __forceinline__ uint32_t sm_u32(const void* p) {
    uint32_t a;
    asm("{ .reg .u64 t; cvta.to.shared.u64 t, %1; cvt.u32.u64 %0, t; }" : "=r"(a) : "l"(p));
    return a;
}
__device__ __forceinline__ void cp16(uint32_t dst, const void* src) {
    asm volatile("cp.async.cg.shared.global [%0], [%1], 16;" :: "r"(dst), "l"(src));
}
__device__ __forceinline__ void mma_f16(float c[4], const uint32_t a[4],
                                        const uint32_t b[2]) {
    asm volatile(
        "mma.sync.aligned.m16n8k16.row.col.f32.f16.f16.f32 "
        "{%0,%1,%2,%3}, {%4,%5,%6,%7}, {%8,%9}, {%0,%1,%2,%3};\n"
        : "+f"(c[0]), "+f"(c[1]), "+f"(c[2]), "+f"(c[3])
        : "r"(a[0]), "r"(a[1]), "r"(a[2]), "r"(a[3]), "r"(b[0]), "r"(b[1]));
}
__device__ __forceinline__ void ldmx4(uint32_t r[4], uint32_t addr) {
    asm volatile("ldmatrix.sync.aligned.m8n8.x4.shared.b16 {%0,%1,%2,%3}, [%4];"
                 : "=r"(r[0]), "=r"(r[1]), "=r"(r[2]), "=r"(r[3]) : "r"(addr));
}
__device__ __forceinline__ void ldmx4t(uint32_t r[4], uint32_t addr) {
    asm volatile("ldmatrix.sync.aligned.m8n8.x4.trans.shared.b16 {%0,%1,%2,%3}, [%4];"
                 : "=r"(r[0]), "=r"(r[1]), "=r"(r[2]), "=r"(r[3]) : "r"(addr));
}

// ---------------------------------------------------------------------------
// Small kernels (unchanged from R14)
// ---------------------------------------------------------------------------
__global__ void convert_w_kernel(const float* __restrict__ wq, const float* __restrict__ wp,
                                 __half* __restrict__ oq, __half* __restrict__ op) {
    int i = blockIdx.x * 256 + threadIdx.x;
    const int NQ = 3 * CDIM * CDIM;
    if (i < NQ) oq[i] = __float2half(wq[i]);
    else        op[i - NQ] = __float2half(wp[i - NQ]);
}

__global__ void gn_stats_kernel(const float* __restrict__ x, float* __restrict__ stats) {
    const int b = blockIdx.x >> 3;
    const int g = blockIdx.x & 7;
    const float4* xb = (const float4*)(x + ((size_t)b * CDIM + (size_t)g * 64) * NPIX);
    const int tid = threadIdx.x;
    const int NG4 = 64 * NPIX / 4;

    float s = 0.f, ss = 0.f;
    for (int i = tid; i < NG4; i += 256) {
        float4 v = xb[i];
        s  += v.x + v.y + v.z + v.w;
        ss += v.x * v.x + v.y * v.y + v.z * v.z + v.w * v.w;
    }
    #pragma unroll
    for (int o = 16; o > 0; o >>= 1) {
        s  += __shfl_xor_sync(0xffffffffu, s, o);
        ss += __shfl_xor_sync(0xffffffffu, ss, o);
    }
    __shared__ float sh_s[8], sh_ss[8];
    if ((tid & 31) == 0) { sh_s[tid >> 5] = s; sh_ss[tid >> 5] = ss; }
    __syncthreads();
    if (tid == 0) {
        float s2 = 0.f, ss2 = 0.f;
        #pragma unroll
        for (int i = 0; i < 8; i++) { s2 += sh_s[i]; ss2 += sh_ss[i]; }
        const float mean = s2 * (1.f / 65536.f);
        const float var  = ss2 * (1.f / 65536.f) - mean * mean;
        stats[blockIdx.x * 2 + 0] = mean;
        stats[blockIdx.x * 2 + 1] = rsqrtf(var + 1e-5f);
    }
}

__global__ void gn_apply_T(const float* __restrict__ x, const float* __restrict__ stats,
                           const float* __restrict__ gamma, const float* __restrict__ beta,
                           __half* __restrict__ hT) {
    __shared__ float sm[64][65];
    __shared__ float sc[64], sf[64];
    const int b = blockIdx.z;
    const int c0 = blockIdx.x * 64, n0 = blockIdx.y * 64;
    const int tid = threadIdx.x;

    if (tid < 64) {
        const int c = c0 + tid;
        const float mean = stats[(b * 8 + (c >> 6)) * 2 + 0];
        const float rstd = stats[(b * 8 + (c >> 6)) * 2 + 1];
        const float g = gamma[c];
        sc[tid] = rstd * g;
        sf[tid] = beta[c] - mean * rstd * g;
    }
    __syncthreads();

    const float* xb = x + (size_t)b * CDIM * NPIX;
    #pragma unroll
    for (int p = 0; p < 16; p++) {
        const int idx = tid + p * 256;
        const int r = idx >> 6, col = idx & 63;
        sm[r][col] = xb[(size_t)(c0 + r) * NPIX + n0 + col] * sc[r] + sf[r];
    }
    __syncthreads();

    const int l = tid & 31;
    #pragma unroll
    for (int p = 0; p < 8; p++) {
        const int tn = (tid >> 5) + p * 8;
        __half2 v = __floats2half2_rn(sm[2 * l][tn], sm[2 * l + 1][tn]);
        *(__half2*)(hT + (size_t)(b * NPIX + n0 + tn) * CDIM + c0 + 2 * l) = v;
    }
}

__global__ void softmax_kernel(__half* __restrict__ attnH) {
    const int warp = threadIdx.x >> 5, lane = threadIdx.x & 31;
    __half2* row = (__half2*)(attnH + ((size_t)blockIdx.x * 4 + warp) * NPIX);

    float2 v[16];
    float mx = -1e30f;
    #pragma unroll
    for (int i = 0; i < 16; i++) {
        v[i] = __half22float2(row[lane + i * 32]);
        mx = fmaxf(mx, fmaxf(v[i].x, v[i].y));
    }
    #pragma unroll
    for (int o = 16; o > 0; o >>= 1)
        mx = fmaxf(mx, __shfl_xor_sync(0xffffffffu, mx, o));

    float s = 0.f;
    #pragma unroll
    for (int i = 0; i < 16; i++) {
        v[i].x = __expf(v[i].x - mx);
        v[i].y = __expf(v[i].y - mx);
        s += v[i].x + v[i].y;
    }
    #pragma unroll
    for (int o = 16; o > 0; o >>= 1)
        s += __shfl_xor_sync(0xffffffffu, s, o);

    const float inv = 1.f / s;
    #pragma unroll
    for (int i = 0; i < 16; i++)
        row[lane + i * 32] = __floats2half2_rn(v[i].x * inv, v[i].y * inv);
}

// ---------------------------------------------------------------------------
// FP16 GEMM (fp32 accumulate), ldmatrix fragment loads, software-pipelined
// fragments (A double-buffered across k16 slices, B reloaded mid-slice).
//   D[bz, m, n] = alpha * sum_k A[m][k] * B_k_n (+bias_m[m]) (+bias_n[n]) (+resid)
// Tile 128x128x64, 256 threads, 8 warps (2m x 4n), warp tile 64x32.
// 3-stage cp.async, 2 CTAs/SM.
// ---------------------------------------------------------------------------
#define BM 128
#define BN 128
#define BKH 64
#define STAGES 3
#define LDAH 72                     // halves per A smem row (64 + 8 pad)
#define LDBT 136                    // halves per trans-B smem row (128 + 8 pad)
#define A_STG_B (BM * LDAH * 2)     // 18432 bytes
#define B_STG_N (BN * LDAH * 2)     // 18432 bytes (BT=0)
#define B_STG_T (BKH * LDBT * 2)    // 17408 bytes (BT=1)
#define SMEM_N (STAGES * (A_STG_B + B_STG_N))   // 110592
#define SMEM_T (STAGES * (A_STG_B + B_STG_T))   // 107520

template <int BT>
__global__ __launch_bounds__(256, 2)
void hgemm(const __half* __restrict__ A, const __half* __restrict__ B,
           float* __restrict__ Cf, __half* __restrict__ Ch,
           const float* __restrict__ bias_m, const float* __restrict__ bias_n,
           const float* __restrict__ resid,
           int Kdim, long a_rs, long a_zs, long b_rs, long b_zs,
           long c_ms, long c_zs, float alpha) {
    extern __shared__ char smem_raw[];
    const uint32_t as_base = sm_u32(smem_raw);
    const uint32_t bs_base = as_base + STAGES * A_STG_B;
    const int BSTG = BT ? B_STG_T : B_STG_N;

    const int tid = threadIdx.x, warp = tid >> 5, lane = tid & 31;
    const int gid = lane >> 2, tig = lane & 3;
    const int bx = blockIdx.x, by = blockIdx.y, bz = blockIdx.z;
    const int wm = (warp & 1) * 64;
    const int wn = (warp >> 1) * 32;
    const int lr = lane & 7, mi = lane >> 3;

    // per-thread ldmatrix byte offsets (loop-invariant)
    uint32_t af_off[4], bf_off[2];
    #pragma unroll
    for (int i = 0; i < 4; i++)
        af_off[i] = 2u * (uint32_t)((wm + i * 16 + (mi & 1) * 8 + lr) * LDAH + (mi >> 1) * 8);
    #pragma unroll
    for (int j2 = 0; j2 < 2; j2++) {
        if (BT)
            bf_off[j2] = 2u * (uint32_t)((lr + (mi & 1) * 8) * LDBT + wn + j2 * 16 + (mi >> 1) * 8);
        else
            bf_off[j2] = 2u * (uint32_t)((wn + j2 * 16 + (mi >> 1) * 8 + lr) * LDAH + (mi & 1) * 8);
    }

    const __half* Ab = A + (size_t)bz * a_zs + (size_t)by * BM * a_rs;
    const __half* Bb = BT ? (B + (size_t)bz * b_zs + (size_t)bx * BN)
                          : (B + (size_t)bz * b_zs + (size_t)bx * BN * b_rs);

    float acc[4][4][4];
    #pragma unroll
    for (int i = 0; i < 4; i++)
        #pragma unroll
        for (int j = 0; j < 4; j++)
            #pragma unroll
            for (int r = 0; r < 4; r++) acc[i][j][r] = 0.f;

    auto fill = [&](int t) {
        const int s = t % STAGES;
        const __half* ag = Ab + (size_t)t * BKH;
        const uint32_t ad = as_base + s * A_STG_B;
        #pragma unroll
        for (int i = 0; i < 4; i++) {
            int idx = tid + i * 256;
            int r = idx >> 3, g = idx & 7;
            cp16(ad + (uint32_t)(r * (LDAH * 2) + g * 16), ag + (size_t)r * a_rs + g * 8);
        }
        const uint32_t bd = bs_base + s * BSTG;
        if (BT) {
            const __half* bg = Bb + (size_t)t * BKH * b_rs;
            #pragma unroll
            for (int i = 0; i < 4; i++) {
                int idx = tid + i * 256;
                int r = idx >> 4, g = idx & 15;
                cp16(bd + (uint32_t)(r * (LDBT * 2) + g * 16), bg + (size_t)r * b_rs + g * 8);
            }
        } else {
            const __half* bg = Bb + (size_t)t * BKH;
            #pragma unroll
            for (int i = 0; i < 4; i++) {
                int idx = tid + i * 256;
                int r = idx >> 3, g = idx & 7;
                cp16(bd + (uint32_t)(r * (LDAH * 2) + g * 16), bg + (size_t)r * b_rs + g * 8);
            }
        }
        asm volatile("cp.async.commit_group;" ::: "memory");
    };

    const int T = Kdim / BKH;
    fill(0);
    if (T > 1) fill(1);

    for (int t = 0; t < T; t++) {
        if (t < T - 1) asm volatile("cp.async.wait_group 1;" ::: "memory");
        else           asm volatile("cp.async.wait_group 0;" ::: "memory");
        __syncthreads();

        if (t + 2 < T) fill(t + 2);

        const int s = t % STAGES;
        const uint32_t as_s = as_base + s * A_STG_B;
        const uint32_t bs_s = bs_base + s * BSTG;

        uint32_t af[2][4][4], bf[4][2];

        // B fragment load for slice at half-offset kh into bf[2*j2 .. 2*j2+1]
        auto loadB = [&](int j2, int kh) {
            uint32_t r[4];
            if (BT) ldmx4t(r, bs_s + bf_off[j2] + (uint32_t)(kh * (LDBT * 2)));
            else    ldmx4 (r, bs_s + bf_off[j2] + (uint32_t)(kh * 2));
            bf[j2 * 2][0] = r[0]; bf[j2 * 2][1] = r[1];
            bf[j2 * 2 + 1][0] = r[2]; bf[j2 * 2 + 1][1] = r[3];
        };

        // prologue: slice 0 fragments
        #pragma unroll
        for (int i = 0; i < 4; i++) ldmx4(af[0][i], as_s + af_off[i]);
        loadB(0, 0);
        loadB(1, 0);

        #pragma unroll
        for (int sl = 0; sl < 4; sl++) {
            const int cur = sl & 1, nxt = cur ^ 1;
            const int khn = (sl + 1) * 16;

            // prefetch next slice's A fragments (double buffer; no WAR on af[cur])
            if (sl < 3) {
                #pragma unroll
                for (int i = 0; i < 4; i++)
                    ldmx4(af[nxt][i], as_s + af_off[i] + (uint32_t)(khn * 2));
            }

            // j2 = 0 group (j = 0,1): last readers of bf[0..1]
            #pragma unroll
            for (int i = 0; i < 4; i++) {
                mma_f16(acc[i][0], af[cur][i], bf[0]);
                mma_f16(acc[i][1], af[cur][i], bf[1]);
            }
            if (sl < 3) loadB(0, khn);   // refill bf[0..1] for next slice

            // j2 = 1 group (j = 2,3): last readers of bf[2..3]
            #pragma unroll
            for (int i = 0; i < 4; i++) {
                mma_f16(acc[i][2], af[cur][i], bf[2]);
                mma_f16(acc[i][3], af[cur][i], bf[3]);
            }
            if (sl < 3) loadB(1, khn);   // refill bf[2..3]
        }
    }

    // ---- epilogue ----
    #pragma unroll
    for (int i = 0; i < 4; i++) {
        const int m0 = by * BM + wm + i * 16 + gid;
        const float bv0 = bias_m ? bias_m[m0] : 0.f;
        const float bv1 = bias_m ? bias_m[m0 + 8] : 0.f;
        #pragma unroll
        for (int j = 0; j < 4; j++) {
            const int n0 = bx * BN + wn + j * 8 + tig * 2;
            const float bn0 = bias_n ? bias_n[n0] : 0.f;
            const float bn1 = bias_n ? bias_n[n0 + 1] : 0.f;
            size_t o0 = (size_t)bz * c_zs + (size_t)m0 * c_ms + n0;
            size_t o1 = o0 + 8 * c_ms;
            float v0 = acc[i][j][0] * alpha + bv0 + bn0;
            float v1 = acc[i][j][1] * alpha + bv0 + bn1;
            float v2 = acc[i][j][2] * alpha + bv1 + bn0;
            float v3 = acc[i][j][3] * alpha + bv1 + bn1;
            if (resid) {
                v0 += resid[o0]; v1 += resid[o0 + 1];
                v2 += resid[o1]; v3 += resid[o1 + 1];
            }
            if (Ch) {
                *(__half2*)(Ch + o0) = __floats2half2_rn(v0, v1);
                *(__half2*)(Ch + o1) = __floats2half2_rn(v2, v3);
            } else {
                *(float2*)(Cf + o0) = make_float2(v0, v1);
                *(float2*)(Cf + o1) = make_float2(v2, v3);
            }
        }
    }
}

// ---------------------------------------------------------------------------
// Launch
// ---------------------------------------------------------------------------
extern "C" void kernel_launch(void* const* d_in, const int* in_sizes, int n_in,
                              void* d_out, int out_size) {
    const float* x      = (const float*)d_in[0];
    const float* gamma  = (const float*)d_in[1];
    const float* beta   = (const float*)d_in[2];
    const float* w_qkv  = (const float*)d_in[3];
    const float* b_qkv  = (const float*)d_in[4];
    const float* w_proj = (const float*)d_in[5];
    const float* b_proj = (const float*)d_in[6];
    float* out = (float*)d_out;

    float *stats;
    __half *hT, *wqkvH, *wprojH, *qkvT, *attnH, *obT;
    cudaGetSymbolAddress((void**)&stats,  g_stats);
    cudaGetSymbolAddress((void**)&hT,     g_hT);
    cudaGetSymbolAddress((void**)&wqkvH,  g_wqkvH);
    cudaGetSymbolAddress((void**)&wprojH, g_wprojH);
    cudaGetSymbolAddress((void**)&qkvT,   g_qkvT);
    cudaGetSymbolAddress((void**)&attnH,  g_attnH);
    cudaGetSymbolAddress((void**)&obT,    g_obT);

    cudaFuncSetAttribute(hgemm<0>, cudaFuncAttributeMaxDynamicSharedMemorySize, SMEM_N);
    cudaFuncSetAttribute(hgemm<1>, cudaFuncAttributeMaxDynamicSharedMemorySize, SMEM_T);

    const float scale = 1.0f / sqrtf((float)CDIM);

    // 0) convert both weight matrices to half (one launch)
    convert_w_kernel<<<(4 * CDIM * CDIM) / 256, 256>>>(w_qkv, w_proj, wqkvH, wprojH);

    // 1) GroupNorm stats, then fused normalize+transpose -> hT[t][c] half
    gn_stats_kernel<<<BATCH * 8, 256>>>(x, stats);
    gn_apply_T<<<dim3(CDIM / 64, NPIX / 64, BATCH), 256>>>(x, stats, gamma, beta, hT);

    // 2) QKV: qkvT[t][o] = sum_c hT[t][c] * wqkvH[o][c] + b_qkv[o]
    hgemm<0><<<dim3(1536 / BN, MCOLS / BM, 1), 256, SMEM_N>>>(
        hT, wqkvH, nullptr, qkvT, nullptr, b_qkv, nullptr,
        CDIM, /*a_rs*/ CDIM, 0, /*b_rs*/ CDIM, 0,
        /*c_ms*/ 1536, 0, 1.0f);

    // 3) Scores (half out): attnH[b][i][j] = scale * sum_c q[i][c] * k[j][c]
    hgemm<0><<<dim3(NPIX / BN, NPIX / BM, BATCH), 256, SMEM_N>>>(
        qkvT, qkvT + 512, nullptr, attnH, nullptr, nullptr, nullptr,
        CDIM, /*a_rs*/ 1536, /*a_zs*/ (long)NPIX * 1536,
        /*b_rs*/ 1536, /*b_zs*/ (long)NPIX * 1536,
        /*c_ms*/ NPIX, (long)NPIX * NPIX, scale);

    // 4) Softmax in place (half), warp-per-row
    softmax_kernel<<<BATCH * NPIX / 4, 128>>>(attnH);

    // 5) PV (trans-B): obT[b*1024+i][c] = sum_j attnH[b][i][j] * v[b*1024+j][c]
    hgemm<1><<<dim3(CDIM / BN, NPIX / BM, BATCH), 256, SMEM_T>>>(
        attnH, qkvT + 1024, nullptr, obT, nullptr, nullptr, nullptr,
        NPIX, /*a_rs*/ NPIX, /*a_zs*/ (long)NPIX * NPIX,
        /*b_rs*/ 1536, /*b_zs*/ (long)NPIX * 1536,
        /*c_ms*/ CDIM, (long)NPIX * CDIM, 1.0f);

    // 6) Proj: out[b][o][n] = sum_c wprojH[o][c] * obT[b*1024+n][c] + b_proj[o] + x
    hgemm<0><<<dim3(NPIX / BN, CDIM / BM, BATCH), 256, SMEM_N>>>(
        wprojH, obT, out, nullptr, b_proj, nullptr, x,
        CDIM, /*a_rs*/ CDIM, 0, /*b_rs*/ CDIM, /*b_zs*/ (long)NPIX * CDIM,
        /*c_ms*/ NPIX, (long)CDIM * NPIX, 1.0f);
}

// round 17
// speedup vs baseline: 3.7401x; 1.0010x over previous
#include <cuda_runtime.h>
#include <cuda_fp16.h>
#include <math.h>
#include <stdint.h>

#define CDIM 512
#define BATCH 16
#define NPIX 1024
#define MCOLS (BATCH * NPIX)   // 16384

// ---------------------------------------------------------------------------
// Scratch (device globals)
// ---------------------------------------------------------------------------
__device__ float  g_stats [BATCH * 8 * 2];                 // mean, rstd per (b,g)
__device__ __half g_hT    [(size_t)MCOLS * CDIM];          // [t][c]
__device__ __half g_wqkvH [(size_t)3 * CDIM * CDIM];       // [o][c]
__device__ __half g_wprojH[(size_t)CDIM * CDIM];           // [o][c]
__device__ __half g_qkvT  [(size_t)MCOLS * 3 * CDIM];      // [t][o]  q|k|v
__device__ __half g_attnH [(size_t)BATCH * NPIX * NPIX];   // [b][i][j] scores -> probs
__device__ __half g_obT   [(size_t)MCOLS * CDIM];          // [t][c]

// ---------------------------------------------------------------------------
// Helpers
// ---------------------------------------------------------------------------
__device__ __forceinline__ uint32_t sm_u32(const void* p) {
    uint32_t a;
    asm("{ .reg .u64 t; cvta.to.shared.u64 t, %1; cvt.u32.u64 %0, t; }" : "=r"(a) : "l"(p));
    return a;
}
__device__ __forceinline__ void cp16(uint32_t dst, const void* src) {
    asm volatile("cp.async.cg.shared.global [%0], [%1], 16;" :: "r"(dst), "l"(src));
}
__device__ __forceinline__ void mma_f16(float c[4], const uint32_t a[4],
                                        const uint32_t b[2]) {
    asm volatile(
        "mma.sync.aligned.m16n8k16.row.col.f32.f16.f16.f32 "
        "{%0,%1,%2,%3}, {%4,%5,%6,%7}, {%8,%9}, {%0,%1,%2,%3};\n"
        : "+f"(c[0]), "+f"(c[1]), "+f"(c[2]), "+f"(c[3])
        : "r"(a[0]), "r"(a[1]), "r"(a[2]), "r"(a[3]), "r"(b[0]), "r"(b[1]));
}
__device__ __forceinline__ void ldmx4(uint32_t r[4], uint32_t addr) {
    asm volatile("ldmatrix.sync.aligned.m8n8.x4.shared.b16 {%0,%1,%2,%3}, [%4];"
                 : "=r"(r[0]), "=r"(r[1]), "=r"(r[2]), "=r"(r[3]) : "r"(addr));
}
__device__ __forceinline__ void ldmx4t(uint32_t r[4], uint32_t addr) {
    asm volatile("ldmatrix.sync.aligned.m8n8.x4.trans.shared.b16 {%0,%1,%2,%3}, [%4];"
                 : "=r"(r[0]), "=r"(r[1]), "=r"(r[2]), "=r"(r[3]) : "r"(addr));
}

// ---------------------------------------------------------------------------
// Small kernels (unchanged)
// ---------------------------------------------------------------------------
__global__ void convert_w_kernel(const float* __restrict__ wq, const float* __restrict__ wp,
                                 __half* __restrict__ oq, __half* __restrict__ op) {
    int i = blockIdx.x * 256 + threadIdx.x;
    const int NQ = 3 * CDIM * CDIM;
    if (i < NQ) oq[i] = __float2half(wq[i]);
    else        op[i - NQ] = __float2half(wp[i - NQ]);
}

__global__ void gn_stats_kernel(const float* __restrict__ x, float* __restrict__ stats) {
    const int b = blockIdx.x >> 3;
    const int g = blockIdx.x & 7;
    const float4* xb = (const float4*)(x + ((size_t)b * CDIM + (size_t)g * 64) * NPIX);
    const int tid = threadIdx.x;
    const int NG4 = 64 * NPIX / 4;

    float s = 0.f, ss = 0.f;
    for (int i = tid; i < NG4; i += 256) {
        float4 v = xb[i];
        s  += v.x + v.y + v.z + v.w;
        ss += v.x * v.x + v.y * v.y + v.z * v.z + v.w * v.w;
    }
    #pragma unroll
    for (int o = 16; o > 0; o >>= 1) {
        s  += __shfl_xor_sync(0xffffffffu, s, o);
        ss += __shfl_xor_sync(0xffffffffu, ss, o);
    }
    __shared__ float sh_s[8], sh_ss[8];
    if ((tid & 31) == 0) { sh_s[tid >> 5] = s; sh_ss[tid >> 5] = ss; }
    __syncthreads();
    if (tid == 0) {
        float s2 = 0.f, ss2 = 0.f;
        #pragma unroll
        for (int i = 0; i < 8; i++) { s2 += sh_s[i]; ss2 += sh_ss[i]; }
        const float mean = s2 * (1.f / 65536.f);
        const float var  = ss2 * (1.f / 65536.f) - mean * mean;
        stats[blockIdx.x * 2 + 0] = mean;
        stats[blockIdx.x * 2 + 1] = rsqrtf(var + 1e-5f);
    }
}

__global__ void gn_apply_T(const float* __restrict__ x, const float* __restrict__ stats,
                           const float* __restrict__ gamma, const float* __restrict__ beta,
                           __half* __restrict__ hT) {
    __shared__ float sm[64][65];
    __shared__ float sc[64], sf[64];
    const int b = blockIdx.z;
    const int c0 = blockIdx.x * 64, n0 = blockIdx.y * 64;
    const int tid = threadIdx.x;

    if (tid < 64) {
        const int c = c0 + tid;
        const float mean = stats[(b * 8 + (c >> 6)) * 2 + 0];
        const float rstd = stats[(b * 8 + (c >> 6)) * 2 + 1];
        const float g = gamma[c];
        sc[tid] = rstd * g;
        sf[tid] = beta[c] - mean * rstd * g;
    }
    __syncthreads();

    const float* xb = x + (size_t)b * CDIM * NPIX;
    #pragma unroll
    for (int p = 0; p < 16; p++) {
        const int idx = tid + p * 256;
        const int r = idx >> 6, col = idx & 63;
        sm[r][col] = xb[(size_t)(c0 + r) * NPIX + n0 + col] * sc[r] + sf[r];
    }
    __syncthreads();

    const int l = tid & 31;
    #pragma unroll
    for (int p = 0; p < 8; p++) {
        const int tn = (tid >> 5) + p * 8;
        __half2 v = __floats2half2_rn(sm[2 * l][tn], sm[2 * l + 1][tn]);
        *(__half2*)(hT + (size_t)(b * NPIX + n0 + tn) * CDIM + c0 + 2 * l) = v;
    }
}

__global__ void softmax_kernel(__half* __restrict__ attnH) {
    const int warp = threadIdx.x >> 5, lane = threadIdx.x & 31;
    __half2* row = (__half2*)(attnH + ((size_t)blockIdx.x * 4 + warp) * NPIX);

    float2 v[16];
    float mx = -1e30f;
    #pragma unroll
    for (int i = 0; i < 16; i++) {
        v[i] = __half22float2(row[lane + i * 32]);
        mx = fmaxf(mx, fmaxf(v[i].x, v[i].y));
    }
    #pragma unroll
    for (int o = 16; o > 0; o >>= 1)
        mx = fmaxf(mx, __shfl_xor_sync(0xffffffffu, mx, o));

    float s = 0.f;
    #pragma unroll
    for (int i = 0; i < 16; i++) {
        v[i].x = __expf(v[i].x - mx);
        v[i].y = __expf(v[i].y - mx);
        s += v[i].x + v[i].y;
    }
    #pragma unroll
    for (int o = 16; o > 0; o >>= 1)
        s += __shfl_xor_sync(0xffffffffu, s, o);

    const float inv = 1.f / s;
    #pragma unroll
    for (int i = 0; i < 16; i++)
        row[lane + i * 32] = __floats2half2_rn(v[i].x * inv, v[i].y * inv);
}

// ---------------------------------------------------------------------------
// FP16 GEMM (fp32 accumulate). 128 threads, 4 warps (2m x 2n), warp tile 64x64
// -> 1.5x less smem fragment traffic per MAC than 64x32. 2 CTAs/SM (256 regs/thr).
// Tile 128x128x64, 3-stage cp.async, A-fragment double buffering, B refilled
// per j2 group after last use.
// ---------------------------------------------------------------------------
#define BM 128
#define BN 128
#define BKH 64
#define STAGES 3
#define LDAH 72                     // halves per A smem row (64 + 8 pad)
#define LDBT 136                    // halves per trans-B smem row (128 + 8 pad)
#define A_STG_B (BM * LDAH * 2)     // 18432 bytes
#define B_STG_N (BN * LDAH * 2)     // 18432 bytes (BT=0)
#define B_STG_T (BKH * LDBT * 2)    // 17408 bytes (BT=1)
#define SMEM_N (STAGES * (A_STG_B + B_STG_N))   // 110592
#define SMEM_T (STAGES * (A_STG_B + B_STG_T))   // 107520
#define NTHR 128

template <int BT>
__global__ __launch_bounds__(NTHR, 2)
void hgemm(const __half* __restrict__ A, const __half* __restrict__ B,
           float* __restrict__ Cf, __half* __restrict__ Ch,
           const float* __restrict__ bias_m, const float* __restrict__ bias_n,
           const float* __restrict__ resid,
           int Kdim, long a_rs, long a_zs, long b_rs, long b_zs,
           long c_ms, long c_zs, float alpha) {
    extern __shared__ char smem_raw[];
    const uint32_t as_base = sm_u32(smem_raw);
    const uint32_t bs_base = as_base + STAGES * A_STG_B;
    const int BSTG = BT ? B_STG_T : B_STG_N;

    const int tid = threadIdx.x, warp = tid >> 5, lane = tid & 31;
    const int gid = lane >> 2, tig = lane & 3;
    const int bx = blockIdx.x, by = blockIdx.y, bz = blockIdx.z;
    const int wm = (warp & 1) * 64;
    const int wn = (warp >> 1) * 64;
    const int lr = lane & 7, mi = lane >> 3;

    // loop-invariant ldmatrix byte offsets
    uint32_t af_off[4], bf_off[4];
    #pragma unroll
    for (int i = 0; i < 4; i++)
        af_off[i] = 2u * (uint32_t)((wm + i * 16 + (mi & 1) * 8 + lr) * LDAH + (mi >> 1) * 8);
    #pragma unroll
    for (int j2 = 0; j2 < 4; j2++) {
        if (BT)
            bf_off[j2] = 2u * (uint32_t)((lr + (mi & 1) * 8) * LDBT + wn + j2 * 16 + (mi >> 1) * 8);
        else
            bf_off[j2] = 2u * (uint32_t)((wn + j2 * 16 + (mi >> 1) * 8 + lr) * LDAH + (mi & 1) * 8);
    }

    const __half* Ab = A + (size_t)bz * a_zs + (size_t)by * BM * a_rs;
    const __half* Bb = BT ? (B + (size_t)bz * b_zs + (size_t)bx * BN)
                          : (B + (size_t)bz * b_zs + (size_t)bx * BN * b_rs);

    float acc[4][8][4];
    #pragma unroll
    for (int i = 0; i < 4; i++)
        #pragma unroll
        for (int j = 0; j < 8; j++)
            #pragma unroll
            for (int r = 0; r < 4; r++) acc[i][j][r] = 0.f;

    auto fill = [&](int t) {
        const int s = t % STAGES;
        const __half* ag = Ab + (size_t)t * BKH;
        const uint32_t ad = as_base + s * A_STG_B;
        #pragma unroll
        for (int i = 0; i < 8; i++) {
            int idx = tid + i * NTHR;
            int r = idx >> 3, g = idx & 7;
            cp16(ad + (uint32_t)(r * (LDAH * 2) + g * 16), ag + (size_t)r * a_rs + g * 8);
        }
        const uint32_t bd = bs_base + s * BSTG;
        if (BT) {
            const __half* bg = Bb + (size_t)t * BKH * b_rs;
            #pragma unroll
            for (int i = 0; i < 8; i++) {
                int idx = tid + i * NTHR;
                int r = idx >> 4, g = idx & 15;
                cp16(bd + (uint32_t)(r * (LDBT * 2) + g * 16), bg + (size_t)r * b_rs + g * 8);
            }
        } else {
            const __half* bg = Bb + (size_t)t * BKH;
            #pragma unroll
            for (int i = 0; i < 8; i++) {
                int idx = tid + i * NTHR;
                int r = idx >> 3, g = idx & 7;
                cp16(bd + (uint32_t)(r * (LDAH * 2) + g * 16), bg + (size_t)r * b_rs + g * 8);
            }
        }
        asm volatile("cp.async.commit_group;" ::: "memory");
    };

    const int T = Kdim / BKH;
    fill(0);
    if (T > 1) fill(1);

    for (int t = 0; t < T; t++) {
        if (t < T - 1) asm volatile("cp.async.wait_group 1;" ::: "memory");
        else           asm volatile("cp.async.wait_group 0;" ::: "memory");
        __syncthreads();

        if (t + 2 < T) fill(t + 2);

        const int s = t % STAGES;
        const uint32_t as_s = as_base + s * A_STG_B;
        const uint32_t bs_s = bs_base + s * BSTG;

        uint32_t af[2][4][4], bf[8][2];

        auto loadB = [&](int j2, int kh) {
            uint32_t r[4];
            if (BT) ldmx4t(r, bs_s + bf_off[j2] + (uint32_t)(kh * (LDBT * 2)));
            else    ldmx4 (r, bs_s + bf_off[j2] + (uint32_t)(kh * 2));
            bf[j2 * 2][0] = r[0]; bf[j2 * 2][1] = r[1];
            bf[j2 * 2 + 1][0] = r[2]; bf[j2 * 2 + 1][1] = r[3];
        };

        // prologue: slice 0 fragments
        #pragma unroll
        for (int i = 0; i < 4; i++) ldmx4(af[0][i], as_s + af_off[i]);
        #pragma unroll
        for (int j2 = 0; j2 < 4; j2++) loadB(j2, 0);

        #pragma unroll
        for (int sl = 0; sl < 4; sl++) {
            const int cur = sl & 1, nxt = cur ^ 1;
            const int khn = (sl + 1) * 16;

            if (sl < 3) {
                #pragma unroll
                for (int i = 0; i < 4; i++)
                    ldmx4(af[nxt][i], as_s + af_off[i] + (uint32_t)(khn * 2));
            }

            #pragma unroll
            for (int j2 = 0; j2 < 4; j2++) {
                #pragma unroll
                for (int i = 0; i < 4; i++) {
                    mma_f16(acc[i][j2 * 2],     af[cur][i], bf[j2 * 2]);
                    mma_f16(acc[i][j2 * 2 + 1], af[cur][i], bf[j2 * 2 + 1]);
                }
                if (sl < 3) loadB(j2, khn);   // refill after last use this slice
            }
        }
    }

    // ---- epilogue ----
    #pragma unroll
    for (int i = 0; i < 4; i++) {
        const int m0 = by * BM + wm + i * 16 + gid;
        const float bv0 = bias_m ? bias_m[m0] : 0.f;
        const float bv1 = bias_m ? bias_m[m0 + 8] : 0.f;
        #pragma unroll
        for (int j = 0; j < 8; j++) {
            const int n0 = bx * BN + wn + j * 8 + tig * 2;
            const float bn0 = bias_n ? bias_n[n0] : 0.f;
            const float bn1 = bias_n ? bias_n[n0 + 1] : 0.f;
            size_t o0 = (size_t)bz * c_zs + (size_t)m0 * c_ms + n0;
            size_t o1 = o0 + 8 * c_ms;
            float v0 = acc[i][j][0] * alpha + bv0 + bn0;
            float v1 = acc[i][j][1] * alpha + bv0 + bn1;
            float v2 = acc[i][j][2] * alpha + bv1 + bn0;
            float v3 = acc[i][j][3] * alpha + bv1 + bn1;
            if (resid) {
                v0 += resid[o0]; v1 += resid[o0 + 1];
                v2 += resid[o1]; v3 += resid[o1 + 1];
            }
            if (Ch) {
                *(__half2*)(Ch + o0) = __floats2half2_rn(v0, v1);
                *(__half2*)(Ch + o1) = __floats2half2_rn(v2, v3);
            } else {
                *(float2*)(Cf + o0) = make_float2(v0, v1);
                *(float2*)(Cf + o1) = make_float2(v2, v3);
            }
        }
    }
}

// ---------------------------------------------------------------------------
// Launch
// ---------------------------------------------------------------------------
extern "C" void kernel_launch(void* const* d_in, const int* in_sizes, int n_in,
                              void* d_out, int out_size) {
    const float* x      = (const float*)d_in[0];
    const float* gamma  = (const float*)d_in[1];
    const float* beta   = (const float*)d_in[2];
    const float* w_qkv  = (const float*)d_in[3];
    const float* b_qkv  = (const float*)d_in[4];
    const float* w_proj = (const float*)d_in[5];
    const float* b_proj = (const float*)d_in[6];
    float* out = (float*)d_out;

    float *stats;
    __half *hT, *wqkvH, *wprojH, *qkvT, *attnH, *obT;
    cudaGetSymbolAddress((void**)&stats,  g_stats);
    cudaGetSymbolAddress((void**)&hT,     g_hT);
    cudaGetSymbolAddress((void**)&wqkvH,  g_wqkvH);
    cudaGetSymbolAddress((void**)&wprojH, g_wprojH);
    cudaGetSymbolAddress((void**)&qkvT,   g_qkvT);
    cudaGetSymbolAddress((void**)&attnH,  g_attnH);
    cudaGetSymbolAddress((void**)&obT,    g_obT);

    cudaFuncSetAttribute(hgemm<0>, cudaFuncAttributeMaxDynamicSharedMemorySize, SMEM_N);
    cudaFuncSetAttribute(hgemm<1>, cudaFuncAttributeMaxDynamicSharedMemorySize, SMEM_T);

    const float scale = 1.0f / sqrtf((float)CDIM);

    // 0) convert both weight matrices to half (one launch)
    convert_w_kernel<<<(4 * CDIM * CDIM) / 256, 256>>>(w_qkv, w_proj, wqkvH, wprojH);

    // 1) GroupNorm stats, then fused normalize+transpose -> hT[t][c] half
    gn_stats_kernel<<<BATCH * 8, 256>>>(x, stats);
    gn_apply_T<<<dim3(CDIM / 64, NPIX / 64, BATCH), 256>>>(x, stats, gamma, beta, hT);

    // 2) QKV: qkvT[t][o] = sum_c hT[t][c] * wqkvH[o][c] + b_qkv[o]
    hgemm<0><<<dim3(1536 / BN, MCOLS / BM, 1), NTHR, SMEM_N>>>(
        hT, wqkvH, nullptr, qkvT, nullptr, b_qkv, nullptr,
        CDIM, /*a_rs*/ CDIM, 0, /*b_rs*/ CDIM, 0,
        /*c_ms*/ 1536, 0, 1.0f);

    // 3) Scores (half out): attnH[b][i][j] = scale * sum_c q[i][c] * k[j][c]
    hgemm<0><<<dim3(NPIX / BN, NPIX / BM, BATCH), NTHR, SMEM_N>>>(
        qkvT, qkvT + 512, nullptr, attnH, nullptr, nullptr, nullptr,
        CDIM, /*a_rs*/ 1536, /*a_zs*/ (long)NPIX * 1536,
        /*b_rs*/ 1536, /*b_zs*/ (long)NPIX * 1536,
        /*c_ms*/ NPIX, (long)NPIX * NPIX, scale);

    // 4) Softmax in place (half), warp-per-row
    softmax_kernel<<<BATCH * NPIX / 4, 128>>>(attnH);

    // 5) PV (trans-B): obT[b*1024+i][c] = sum_j attnH[b][i][j] * v[b*1024+j][c]
    hgemm<1><<<dim3(CDIM / BN, NPIX / BM, BATCH), NTHR, SMEM_T>>>(
        attnH, qkvT + 1024, nullptr, obT, nullptr, nullptr, nullptr,
        NPIX, /*a_rs*/ NPIX, /*a_zs*/ (long)NPIX * NPIX,
        /*b_rs*/ 1536, /*b_zs*/ (long)NPIX * 1536,
        /*c_ms*/ CDIM, (long)NPIX * CDIM, 1.0f);

    // 6) Proj: out[b][o][n] = sum_c wprojH[o][c] * obT[b*1024+n][c] + b_proj[o] + x
    hgemm<0><<<dim3(NPIX / BN, CDIM / BM, BATCH), NTHR, SMEM_N>>>(
        wprojH, obT, out, nullptr, b_proj, nullptr, x,
        CDIM, /*a_rs*/ CDIM, 0, /*b_rs*/ CDIM, /*b_zs*/ (long)NPIX * CDIM,
        /*c_ms*/ NPIX, (long)CDIM * NPIX, 1.0f);
}